// round 10
// baseline (speedup 1.0000x reference)
#include <cuda_runtime.h>
#include <cuda_bf16.h>
#include <cstdint>

#define NN   20000
#define EE   320000
#define HID  128
#define NCLS 21
#define EPSN 1e-5f
#define RBF_C (-1.7578125f)          /* -0.5/(8/15)^2 */
#define RBF_S (0.53333333333333333f) /* 8/15 */
#define ASTR 136                      /* padded bf16 row stride in GEMM smem tiles */
#define GEMM_SMEM (4 * 128 * ASTR * 2)
#define TSTR 260                      /* T row stride (floats) in edge smem */
#define EDGE_SMEM (32 * TSTR * 4 + 2 * 256 * 16 * 2 + 2 * 64 * 16 * 2 + 64 * 12)

// ---------------- scratch (device globals; no allocation allowed) ----------
__device__ float g_h  [(size_t)NN * HID];   // node features (fp32)
__device__ __nv_bfloat16 g_hhi[(size_t)NN * HID];  // bf16 split of h
__device__ __nv_bfloat16 g_hlo[(size_t)NN * HID];
__device__ float g_P  [(size_t)NN * 512];   // per-node proj [f_dst|s_dst|f_src|s_src]
__device__ float g_agg[(size_t)NN * HID];   // aggregated messages
__device__ __nv_bfloat16 g_Whi[4 * 512 * HID];  // node W transposed [l][n=512][k=128]
__device__ __nv_bfloat16 g_Wlo[4 * 512 * HID];
__device__ __nv_bfloat16 g_Weh[4 * 256 * 16];   // edge W transposed [l][n=256][k=16]
__device__ __nv_bfloat16 g_Wel[4 * 256 * 16];
__device__ float g_cs [HID];                // BN column sums
__device__ float g_cq [HID];                // BN column sumsqs
// CSR scratch
__device__ int   g_cnt   [NN];
__device__ int   g_cursor[NN];
__device__ int   g_esrc  [EE];
__device__ int   g_edst  [EE];
__device__ float g_edist [EE];

// ---------------- helpers --------------------------------------------------
__device__ __forceinline__ float sigf(float x) {
    return __fdividef(1.0f, 1.0f + __expf(-x));
}
__device__ __forceinline__ float spf(float x) {  // softplus, stable
    return fmaxf(x, 0.0f) + __logf(1.0f + __expf(-fabsf(x)));
}
__device__ __forceinline__ void split_bf16(float x, __nv_bfloat16& hi, __nv_bfloat16& lo) {
    hi = __float2bfloat16_rn(x);
    lo = __float2bfloat16_rn(x - __bfloat162float(hi));
}
__device__ __forceinline__ void mma_bf16(float c[4], uint32_t a0, uint32_t a1,
                                         uint32_t a2, uint32_t a3,
                                         uint32_t b0, uint32_t b1) {
    asm volatile(
        "mma.sync.aligned.m16n8k16.row.col.f32.bf16.bf16.f32 "
        "{%0,%1,%2,%3}, {%4,%5,%6,%7}, {%8,%9}, {%0,%1,%2,%3};\n"
        : "+f"(c[0]), "+f"(c[1]), "+f"(c[2]), "+f"(c[3])
        : "r"(a0), "r"(a1), "r"(a2), "r"(a3), "r"(b0), "r"(b1));
}
__device__ __forceinline__ void ldsm_x4(uint32_t& r0, uint32_t& r1, uint32_t& r2,
                                        uint32_t& r3, uint32_t addr) {
    asm volatile("ldmatrix.sync.aligned.m8n8.x4.shared.b16 {%0,%1,%2,%3}, [%4];"
                 : "=r"(r0), "=r"(r1), "=r"(r2), "=r"(r3) : "r"(addr));
}
__device__ __forceinline__ void ldsm_x2(uint32_t& r0, uint32_t& r1, uint32_t addr) {
    asm volatile("ldmatrix.sync.aligned.m8n8.x2.shared.b16 {%0,%1}, [%2];"
                 : "=r"(r0), "=r"(r1) : "r"(addr));
}
__device__ __forceinline__ uint32_t smem_u32(const void* p) {
    return (uint32_t)__cvta_generic_to_shared(p);
}

// ---------------- repack node Wf/Ws into bf16-split TRANSPOSED [4][512][128] -
__global__ void repack_kernel(const float* __restrict__ Wf, const float* __restrict__ Ws) {
    int idx = blockIdx.x * blockDim.x + threadIdx.x;
    const int total = 4 * 512 * HID;
    if (idx >= total) return;
    int l   = idx / (512 * HID);
    int rem = idx - l * (512 * HID);
    int n   = rem >> 7;     // 0..511
    int k   = rem & 127;    // 0..127
    const float* Wfl = Wf + (size_t)l * 272 * HID;
    const float* Wsl = Ws + (size_t)l * 272 * HID;
    float v;
    if      (n < 128) v = Wfl[k * HID + n];
    else if (n < 256) v = Wsl[k * HID + (n - 128)];
    else if (n < 384) v = Wfl[(128 + k) * HID + (n - 256)];
    else              v = Wsl[(128 + k) * HID + (n - 384)];
    __nv_bfloat16 hi, lo;
    split_bf16(v, hi, lo);
    g_Whi[idx] = hi;
    g_Wlo[idx] = lo;
}

// ---------------- repack edge W rows into bf16-split TRANSPOSED [4][256][16] -
__global__ void repack_edge_kernel(const float* __restrict__ Wf, const float* __restrict__ Ws) {
    int idx = blockIdx.x * blockDim.x + threadIdx.x;
    const int total = 4 * 256 * 16;
    if (idx >= total) return;
    int l   = idx / (256 * 16);
    int rem = idx - l * (256 * 16);
    int n   = rem >> 4;     // 0..255
    int k   = rem & 15;     // 0..15
    const float* WfE = Wf + (size_t)l * 272 * HID + 256 * HID;  // [16 k][128 n]
    const float* WsE = Ws + (size_t)l * 272 * HID + 256 * HID;
    float v = (n < 128) ? WfE[k * HID + n] : WsE[k * HID + (n - 128)];
    __nv_bfloat16 hi, lo;
    split_bf16(v, hi, lo);
    g_Weh[idx] = hi;
    g_Wel[idx] = lo;
}

// ---------------- node embedding: h = x @ W_node + b ------------------------
__global__ void embed_kernel(const float* __restrict__ x, const float* __restrict__ Wn,
                             const float* __restrict__ bnode) {
    int gw   = (blockIdx.x * blockDim.x + threadIdx.x) >> 5;
    int lane = threadIdx.x & 31;
    if (gw >= NN) return;
    int j = lane * 4;
    float a[4] = {bnode[j], bnode[j + 1], bnode[j + 2], bnode[j + 3]};
    const float* xr = x + (size_t)gw * 6;
#pragma unroll
    for (int k = 0; k < 6; k++) {
        float xv = xr[k];
        const float* w = Wn + k * HID + j;
        a[0] += xv * w[0]; a[1] += xv * w[1]; a[2] += xv * w[2]; a[3] += xv * w[3];
    }
    *(float4*)(g_h + (size_t)gw * HID + j) = make_float4(a[0], a[1], a[2], a[3]);
#pragma unroll
    for (int t = 0; t < 4; t++) {
        __nv_bfloat16 hi, lo;
        split_bf16(a[t], hi, lo);
        g_hhi[(size_t)gw * HID + j + t] = hi;
        g_hlo[(size_t)gw * HID + j + t] = lo;
    }
}

// ---------------- CSR build --------------------------------------------------
__global__ void csr_zero_kernel() {
    int i = blockIdx.x * blockDim.x + threadIdx.x;
    if (i < NN) g_cnt[i] = 0;
}
__global__ void csr_count_kernel(const int* __restrict__ ei) {
    int e = blockIdx.x * blockDim.x + threadIdx.x;
    if (e < EE) atomicAdd(&g_cnt[ei[EE + e]], 1);
}
__global__ void csr_scan_kernel() {  // single block, 1024 threads
    __shared__ int sums[1024];
    int t = threadIdx.x;
    const int PER = (NN + 1023) / 1024;  // 20
    int base = t * PER;
    int s = 0;
    for (int i = 0; i < PER; i++) {
        int idx = base + i;
        if (idx < NN) s += g_cnt[idx];
    }
    sums[t] = s;
    __syncthreads();
    for (int o = 1; o < 1024; o <<= 1) {
        int v = (t >= o) ? sums[t - o] : 0;
        __syncthreads();
        sums[t] += v;
        __syncthreads();
    }
    int run = sums[t] - s;  // exclusive prefix
    for (int i = 0; i < PER; i++) {
        int idx = base + i;
        if (idx < NN) {
            g_cursor[idx] = run;
            run += g_cnt[idx];
        }
    }
}
__global__ void csr_scatter_kernel(const int* __restrict__ ei, const float* __restrict__ dist) {
    int e = blockIdx.x * blockDim.x + threadIdx.x;
    if (e >= EE) return;
    int src = ei[e];
    int dst = ei[EE + e];
    int pos = atomicAdd(&g_cursor[dst], 1);
    g_esrc[pos]  = src;
    g_edst[pos]  = dst;
    g_edist[pos] = dist[e];
}

// ---------------- tensor-core GEMM: P = h @ W[l]^T, full-K-resident ----------
__global__ __launch_bounds__(512)
void gemm_kernel(int layer, const float* __restrict__ bf_, const float* __restrict__ bs_) {
    extern __shared__ __align__(16) char smem_raw[];
    __nv_bfloat16* Ah = (__nv_bfloat16*)smem_raw;          // [128][ASTR]
    __nv_bfloat16* Al = Ah + 128 * ASTR;
    __nv_bfloat16* Bh = Al + 128 * ASTR;                   // [128 n][ASTR k]
    __nv_bfloat16* Bl = Bh + 128 * ASTR;

    const __nv_bfloat16* Wh = g_Whi + (size_t)layer * 512 * HID;
    const __nv_bfloat16* Wl = g_Wlo + (size_t)layer * 512 * HID;
    int bm = blockIdx.x * 128, bn = blockIdx.y * 128;
    int tid = threadIdx.x;

#pragma unroll
    for (int r = 0; r < 4; r++) {
        int idx = tid + r * 512;          // 0..2047
        int row = idx >> 4, c8 = (idx & 15) * 8;
        int gm = bm + row;
        uint4 vh = make_uint4(0u, 0u, 0u, 0u), vl = vh;
        if (gm < NN) {
            vh = *(const uint4*)&g_hhi[(size_t)gm * HID + c8];
            vl = *(const uint4*)&g_hlo[(size_t)gm * HID + c8];
        }
        *(uint4*)&Ah[row * ASTR + c8] = vh;
        *(uint4*)&Al[row * ASTR + c8] = vl;
    }
#pragma unroll
    for (int r = 0; r < 4; r++) {
        int idx = tid + r * 512;
        int row = idx >> 4, c8 = (idx & 15) * 8;
        *(uint4*)&Bh[row * ASTR + c8] = *(const uint4*)&Wh[(size_t)(bn + row) * HID + c8];
        *(uint4*)&Bl[row * ASTR + c8] = *(const uint4*)&Wl[(size_t)(bn + row) * HID + c8];
    }
    __syncthreads();

    int warp = tid >> 5, lane = tid & 31;
    int wm = (warp >> 2) * 32, wn = (warp & 3) * 32;

    float acc[2][4][4];
#pragma unroll
    for (int mi = 0; mi < 2; mi++)
#pragma unroll
        for (int nj = 0; nj < 4; nj++)
#pragma unroll
            for (int t = 0; t < 4; t++) acc[mi][nj][t] = 0.0f;

    uint32_t aBase = smem_u32(Ah), bBase = smem_u32(Bh);
    const uint32_t HILO_A = (uint32_t)(128 * ASTR * 2);
    int arow = wm + (lane & 15);
    int akof = (lane >> 4) * 8;
    int brow = wn + (lane & 7);
    int bkof = ((lane >> 3) & 1) * 8;

#pragma unroll
    for (int ks = 0; ks < 8; ks++) {
        int k0 = ks * 16;
        uint32_t ah[2][4], al[2][4], bh[4][2], bl[4][2];
#pragma unroll
        for (int mi = 0; mi < 2; mi++) {
            uint32_t ad = aBase + (uint32_t)(((arow + mi * 16) * ASTR + k0 + akof) * 2);
            ldsm_x4(ah[mi][0], ah[mi][1], ah[mi][2], ah[mi][3], ad);
            ldsm_x4(al[mi][0], al[mi][1], al[mi][2], al[mi][3], ad + HILO_A);
        }
#pragma unroll
        for (int nj = 0; nj < 4; nj++) {
            uint32_t bd = bBase + (uint32_t)(((brow + nj * 8) * ASTR + k0 + bkof) * 2);
            ldsm_x2(bh[nj][0], bh[nj][1], bd);
            ldsm_x2(bl[nj][0], bl[nj][1], bd + HILO_A);
        }
#pragma unroll
        for (int mi = 0; mi < 2; mi++)
#pragma unroll
            for (int nj = 0; nj < 4; nj++) {
                mma_bf16(acc[mi][nj], ah[mi][0], ah[mi][1], ah[mi][2], ah[mi][3],
                         bh[nj][0], bh[nj][1]);
                mma_bf16(acc[mi][nj], ah[mi][0], ah[mi][1], ah[mi][2], ah[mi][3],
                         bl[nj][0], bl[nj][1]);
                mma_bf16(acc[mi][nj], al[mi][0], al[mi][1], al[mi][2], al[mi][3],
                         bh[nj][0], bh[nj][1]);
            }
    }

    if (blockIdx.x == 0 && blockIdx.y == 0 && tid < HID) {
        g_cs[tid] = 0.0f;
        g_cq[tid] = 0.0f;
    }

    const float* bptr = (bn == 0) ? bf_ : ((bn == 128) ? bs_ : (const float*)0);
    int crow = lane >> 2, ccol = (lane & 3) * 2;
#pragma unroll
    for (int mi = 0; mi < 2; mi++) {
        int gm0 = bm + wm + mi * 16 + crow;
#pragma unroll
        for (int nj = 0; nj < 4; nj++) {
            int lcol = wn + nj * 8 + ccol;
            float b0 = bptr ? bptr[lcol] : 0.0f;
            float b1 = bptr ? bptr[lcol + 1] : 0.0f;
            int gn = bn + lcol;
            if (gm0 < NN) {
                float2 v = make_float2(acc[mi][nj][0] + b0, acc[mi][nj][1] + b1);
                *(float2*)&g_P[(size_t)gm0 * 512 + gn] = v;
            }
            if (gm0 + 8 < NN) {
                float2 v = make_float2(acc[mi][nj][2] + b0, acc[mi][nj][3] + b1);
                *(float2*)&g_P[(size_t)(gm0 + 8) * 512 + gn] = v;
            }
        }
    }
}

// ---------------- zero agg ----------------------------------------------------
__global__ void zero_kernel() {
    int i = blockIdx.x * blockDim.x + threadIdx.x;
    int stride = gridDim.x * blockDim.x;
    for (int idx = i; idx < NN * HID; idx += stride) g_agg[idx] = 0.0f;
}

// ---------------- edge kernel: 64 CSR edges/block, mma E@W in 2 passes of 32 -
__global__ __launch_bounds__(256, 2)
void edge_kernel(const __nv_bfloat16* __restrict__ Weh, const __nv_bfloat16* __restrict__ Wel) {
    extern __shared__ __align__(16) char esm[];
    float* T = (float*)esm;                                   // [32][TSTR]
    __nv_bfloat16* Wh = (__nv_bfloat16*)(T + 32 * TSTR);      // [256][16]
    __nv_bfloat16* Wl = Wh + 256 * 16;
    __nv_bfloat16* Eh = Wl + 256 * 16;                        // [64][16]
    __nv_bfloat16* El = Eh + 64 * 16;
    int*   s_src  = (int*)(El + 64 * 16);
    int*   s_dst  = s_src + 64;
    float* s_dist = (float*)(s_dst + 64);

    int tid = threadIdx.x;
    int eb = blockIdx.x * 64;
#pragma unroll
    for (int i = tid; i < 512; i += 256) {
        ((uint4*)Wh)[i] = ((const uint4*)Weh)[i];
        ((uint4*)Wl)[i] = ((const uint4*)Wel)[i];
    }
    if (tid < 64) {
        int e = eb + tid;
        s_src[tid]  = g_esrc[e];
        s_dst[tid]  = g_edst[e];
        s_dist[tid] = g_edist[e];
    }
    __syncthreads();
#pragma unroll
    for (int i = tid; i < 1024; i += 256) {
        int le = i >> 4, k = i & 15;
        float t = s_dist[le] - (float)k * RBF_S;
        float v = __expf(RBF_C * t * t);
        __nv_bfloat16 hi, lo;
        split_bf16(v, hi, lo);
        Eh[le * 16 + k] = hi;
        El[le * 16 + k] = lo;
    }
    __syncthreads();

    int warp = tid >> 5, lane = tid & 31;
    int mt = warp >> 2;          // 0..1  : 16-edge tile within the 32-edge pass
    int nq = warp & 3;           // 0..3  : 64-col tile
    uint32_t eBase = smem_u32(Eh), wBase = smem_u32(Wh);
    int c = tid & 31, g = tid >> 5;
    int j4 = c * 4;

#pragma unroll
    for (int p = 0; p < 2; p++) {
        // ---- mma phase: T[0..31][0..255] = E[p*32..+31] @ W^T ----
        uint32_t aAddr = eBase +
            (uint32_t)(((p * 32 + mt * 16 + (lane & 15)) * 16 + (lane >> 4) * 8) * 2);
        uint32_t ah[4], al[4];
        ldsm_x4(ah[0], ah[1], ah[2], ah[3], aAddr);
        ldsm_x4(al[0], al[1], al[2], al[3], aAddr + 2048);   // Eh->El = 64*16*2

        float acc[8][4];
#pragma unroll
        for (int nt = 0; nt < 8; nt++)
#pragma unroll
            for (int t = 0; t < 4; t++) acc[nt][t] = 0.0f;
#pragma unroll
        for (int nt = 0; nt < 8; nt++) {
            int nrow = nq * 64 + nt * 8 + (lane & 7);
            uint32_t bAddr = wBase + (uint32_t)((nrow * 16 + ((lane >> 3) & 1) * 8) * 2);
            uint32_t bh0, bh1, bl0, bl1;
            ldsm_x2(bh0, bh1, bAddr);
            ldsm_x2(bl0, bl1, bAddr + 8192);                 // Wh->Wl = 256*16*2
            mma_bf16(acc[nt], ah[0], ah[1], ah[2], ah[3], bh0, bh1);
            mma_bf16(acc[nt], ah[0], ah[1], ah[2], ah[3], bl0, bl1);
            mma_bf16(acc[nt], al[0], al[1], al[2], al[3], bh0, bh1);
        }
        int crow = mt * 16 + (lane >> 2), ccol = (lane & 3) * 2;
#pragma unroll
        for (int nt = 0; nt < 8; nt++) {
            int col = nq * 64 + nt * 8 + ccol;
            *(float2*)&T[crow * TSTR + col]       = make_float2(acc[nt][0], acc[nt][1]);
            *(float2*)&T[(crow + 8) * TSTR + col] = make_float2(acc[nt][2], acc[nt][3]);
        }
        __syncthreads();

        // ---- epilogue for these 32 edges: 4 edges per thread ----
        int cur = -1, prevdst = -1;
        float m0 = 0.f, m1 = 0.f, m2 = 0.f, m3 = 0.f;
        float4 fd = make_float4(0.f, 0.f, 0.f, 0.f), sd = fd;
#pragma unroll
        for (int i = 0; i < 4; i++) {
            int le = g * 4 + i;             // row in T (0..31)
            int e  = p * 32 + le;           // index into s_src/s_dst
            int src = s_src[e], dst = s_dst[e];
            if (dst != prevdst) {
                const float* pd = g_P + (size_t)dst * 512;
                fd = *(const float4*)(pd + j4);
                sd = *(const float4*)(pd + 128 + j4);
                prevdst = dst;
            }
            const float* ps = g_P + (size_t)src * 512;
            float4 fs = *(const float4*)(ps + 256 + j4);
            float4 ss = *(const float4*)(ps + 384 + j4);
            float4 tf = *(const float4*)&T[le * TSTR + j4];
            float4 ts = *(const float4*)&T[le * TSTR + 128 + j4];
            float f0 = tf.x + fd.x + fs.x;
            float f1 = tf.y + fd.y + fs.y;
            float f2 = tf.z + fd.z + fs.z;
            float f3 = tf.w + fd.w + fs.w;
            float s0 = ts.x + sd.x + ss.x;
            float s1 = ts.y + sd.y + ss.y;
            float s2 = ts.z + sd.z + ss.z;
            float s3 = ts.w + sd.w + ss.w;
            float q0 = sigf(f0) * spf(s0);
            float q1 = sigf(f1) * spf(s1);
            float q2 = sigf(f2) * spf(s2);
            float q3 = sigf(f3) * spf(s3);
            if (dst != cur) {
                if (cur >= 0) {
                    float* ap = g_agg + (size_t)cur * HID + j4;
                    atomicAdd(ap + 0, m0); atomicAdd(ap + 1, m1);
                    atomicAdd(ap + 2, m2); atomicAdd(ap + 3, m3);
                }
                cur = dst;
                m0 = q0; m1 = q1; m2 = q2; m3 = q3;
            } else {
                m0 += q0; m1 += q1; m2 += q2; m3 += q3;
            }
        }
        if (cur >= 0) {
            float* ap = g_agg + (size_t)cur * HID + j4;
            atomicAdd(ap + 0, m0); atomicAdd(ap + 1, m1);
            atomicAdd(ap + 2, m2); atomicAdd(ap + 3, m3);
        }
        __syncthreads();   // T reused next pass
    }
}

// ---------------- BN column stats -------------------------------------------
__global__ void bnstats_kernel() {
    int jj = threadIdx.x;  // 128 threads
    float s = 0.0f, q = 0.0f;
    for (int r = blockIdx.x; r < NN; r += gridDim.x) {
        float v = g_agg[(size_t)r * HID + jj];
        s += v;
        q += v * v;
    }
    atomicAdd(&g_cs[jj], s);
    atomicAdd(&g_cq[jj], q);
}

// ---------------- fused BN + residual + LN + ReLU + residual ----------------
__global__ void update_kernel(const float* __restrict__ bng, const float* __restrict__ bnb,
                              const float* __restrict__ lng, const float* __restrict__ lnb) {
    int gw   = (blockIdx.x * blockDim.x + threadIdx.x) >> 5;
    int lane = threadIdx.x & 31;
    if (gw >= NN) return;
    int j = lane * 4;
    float4 a  = *(const float4*)(g_agg + (size_t)gw * HID + j);
    float4 hv = *(const float4*)(g_h   + (size_t)gw * HID + j);
    float4 cs = *(const float4*)(g_cs + j);
    float4 cq = *(const float4*)(g_cq + j);
    float4 gg = *(const float4*)(bng + j);
    float4 bb = *(const float4*)(bnb + j);
    const float invN = 1.0f / (float)NN;
    float av[4]  = {a.x, a.y, a.z, a.w};
    float hh[4]  = {hv.x, hv.y, hv.z, hv.w};
    float csv[4] = {cs.x, cs.y, cs.z, cs.w};
    float cqv[4] = {cq.x, cq.y, cq.z, cq.w};
    float ggv[4] = {gg.x, gg.y, gg.z, gg.w};
    float bbv[4] = {bb.x, bb.y, bb.z, bb.w};
    float cvals[4];
    float sum = 0.0f, sq = 0.0f;
#pragma unroll
    for (int t = 0; t < 4; t++) {
        float mu  = csv[t] * invN;
        float var = cqv[t] * invN - mu * mu;
        float an  = (av[t] - mu) * rsqrtf(var + EPSN) * ggv[t] + bbv[t];
        cvals[t] = an + hh[t];
        sum += cvals[t];
        sq  += cvals[t] * cvals[t];
    }
#pragma unroll
    for (int o = 16; o; o >>= 1) {
        sum += __shfl_xor_sync(0xffffffffu, sum, o);
        sq  += __shfl_xor_sync(0xffffffffu, sq, o);
    }
    float m  = sum * (1.0f / HID);
    float v  = sq * (1.0f / HID) - m * m;
    float rs = rsqrtf(v + EPSN);
    float4 lg = *(const float4*)(lng + j);
    float4 lb = *(const float4*)(lnb + j);
    float lgv[4] = {lg.x, lg.y, lg.z, lg.w};
    float lbv[4] = {lb.x, lb.y, lb.z, lb.w};
    float o4[4];
#pragma unroll
    for (int t = 0; t < 4; t++)
        o4[t] = fmaxf((cvals[t] - m) * rs * lgv[t] + lbv[t], 0.0f) + hh[t];
    *(float4*)(g_h + (size_t)gw * HID + j) = make_float4(o4[0], o4[1], o4[2], o4[3]);
#pragma unroll
    for (int t = 0; t < 4; t++) {
        __nv_bfloat16 hi, lo;
        split_bf16(o4[t], hi, lo);
        g_hhi[(size_t)gw * HID + j + t] = hi;
        g_hlo[(size_t)gw * HID + j + t] = lo;
    }
}

// ---------------- final LN + FC ---------------------------------------------
__global__ void final_kernel(const float* __restrict__ lng, const float* __restrict__ lnb,
                             const float* __restrict__ Wfc, const float* __restrict__ bfc,
                             float* __restrict__ out) {
    int gw   = (blockIdx.x * blockDim.x + threadIdx.x) >> 5;
    int lane = threadIdx.x & 31;
    if (gw >= NN) return;
    int j = lane * 4;
    float4 hv = *(const float4*)(g_h + (size_t)gw * HID + j);
    float hh[4] = {hv.x, hv.y, hv.z, hv.w};
    float sum = hh[0] + hh[1] + hh[2] + hh[3];
    float sq  = hh[0] * hh[0] + hh[1] * hh[1] + hh[2] * hh[2] + hh[3] * hh[3];
#pragma unroll
    for (int o = 16; o; o >>= 1) {
        sum += __shfl_xor_sync(0xffffffffu, sum, o);
        sq  += __shfl_xor_sync(0xffffffffu, sq, o);
    }
    float m  = sum * (1.0f / HID);
    float v  = sq * (1.0f / HID) - m * m;
    float rs = rsqrtf(v + EPSN);
    float4 lg = *(const float4*)(lng + j);
    float4 lb = *(const float4*)(lnb + j);
    float hn[4];
    hn[0] = (hh[0] - m) * rs * lg.x + lb.x;
    hn[1] = (hh[1] - m) * rs * lg.y + lb.y;
    hn[2] = (hh[2] - m) * rs * lg.z + lb.z;
    hn[3] = (hh[3] - m) * rs * lg.w + lb.w;
#pragma unroll
    for (int c = 0; c < NCLS; c++) {
        float p = hn[0] * Wfc[(j + 0) * NCLS + c]
                + hn[1] * Wfc[(j + 1) * NCLS + c]
                + hn[2] * Wfc[(j + 2) * NCLS + c]
                + hn[3] * Wfc[(j + 3) * NCLS + c];
#pragma unroll
        for (int o = 16; o; o >>= 1) p += __shfl_xor_sync(0xffffffffu, p, o);
        if (lane == 0) out[(size_t)gw * NCLS + c] = p + bfc[c];
    }
}

// ---------------- launch (R8 ordering + edge repack) -------------------------
extern "C" void kernel_launch(void* const* d_in, const int* in_sizes, int n_in,
                              void* d_out, int out_size) {
    const float* x    = (const float*)d_in[0];
    const int*   ei   = (const int*)d_in[1];
    const float* dist = (const float*)d_in[2];
    const float* Wn   = (const float*)d_in[3];
    const float* bnd  = (const float*)d_in[4];
    const float* Wf   = (const float*)d_in[5];
    const float* bf   = (const float*)d_in[6];
    const float* Ws   = (const float*)d_in[7];
    const float* bs   = (const float*)d_in[8];
    const float* bng  = (const float*)d_in[9];
    const float* bnb  = (const float*)d_in[10];
    const float* lng  = (const float*)d_in[11];
    const float* lnb  = (const float*)d_in[12];
    const float* lgo  = (const float*)d_in[13];
    const float* lbo  = (const float*)d_in[14];
    const float* Wfc  = (const float*)d_in[15];
    const float* bfc  = (const float*)d_in[16];
    float* out = (float*)d_out;

    cudaFuncSetAttribute(gemm_kernel, cudaFuncAttributeMaxDynamicSharedMemorySize,
                         GEMM_SMEM);
    cudaFuncSetAttribute(edge_kernel, cudaFuncAttributeMaxDynamicSharedMemorySize,
                         EDGE_SMEM);

    __nv_bfloat16 *dWeh, *dWel;
    cudaGetSymbolAddress((void**)&dWeh, g_Weh);
    cudaGetSymbolAddress((void**)&dWel, g_Wel);

    repack_kernel<<<(4 * 512 * HID + 255) / 256, 256>>>(Wf, Ws);
    repack_edge_kernel<<<(4 * 256 * 16 + 255) / 256, 256>>>(Wf, Ws);
    embed_kernel<<<(NN * 32 + 255) / 256, 256>>>(x, Wn, bnd);
    csr_zero_kernel<<<(NN + 255) / 256, 256>>>();
    csr_count_kernel<<<(EE + 255) / 256, 256>>>(ei);
    csr_scan_kernel<<<1, 1024>>>();
    csr_scatter_kernel<<<(EE + 255) / 256, 256>>>(ei, dist);

    for (int l = 0; l < 4; l++) {
        dim3 gg((NN + 127) / 128, 512 / 128);
        gemm_kernel<<<gg, 512, GEMM_SMEM>>>(l, bf + l * HID, bs + l * HID);
        zero_kernel<<<512, 256>>>();
        edge_kernel<<<EE / 64, 256, EDGE_SMEM>>>(dWeh + (size_t)l * 256 * 16,
                                                 dWel + (size_t)l * 256 * 16);
        bnstats_kernel<<<512, HID>>>();
        update_kernel<<<(NN * 32 + 255) / 256, 256>>>(bng + l * HID, bnb + l * HID,
                                                      lng + l * HID, lnb + l * HID);
    }
    final_kernel<<<(NN * 32 + 255) / 256, 256>>>(lgo, lbo, Wfc, bfc, out);
}

// round 11
// speedup vs baseline: 1.4795x; 1.4795x over previous
#include <cuda_runtime.h>
#include <cuda_bf16.h>
#include <cstdint>

#define NN   20000
#define EE   320000
#define HID  128
#define NCLS 21
#define EPSN 1e-5f
#define RBF_C (-1.7578125f)          /* -0.5/(8/15)^2 */
#define RBF_S (0.53333333333333333f) /* 8/15 */
#define ASTR 136                      /* padded bf16 row stride in smem tiles */
#define GEMM_SMEM (4 * 128 * ASTR * 2)

// ---------------- scratch (device globals; no allocation allowed) ----------
__device__ float g_h  [(size_t)NN * HID];   // node features (fp32)
__device__ __nv_bfloat16 g_hhi[(size_t)NN * HID];  // bf16 split of h
__device__ __nv_bfloat16 g_hlo[(size_t)NN * HID];
__device__ float g_P  [(size_t)NN * 512];   // per-node proj [f_dst|s_dst|f_src|s_src]
__device__ float g_agg[(size_t)NN * HID];   // aggregated messages
__device__ __nv_bfloat16 g_Whi[4 * 512 * HID];  // W transposed [l][n=512][k=128]
__device__ __nv_bfloat16 g_Wlo[4 * 512 * HID];
__device__ float g_cs [HID];                // BN column sums
__device__ float g_cq [HID];                // BN column sumsqs
// CSR scratch
__device__ int   g_cnt   [NN];
__device__ int   g_cursor[NN];
__device__ int   g_esrc  [EE];
__device__ int   g_edst  [EE];
__device__ float g_edist [EE];

// ---------------- helpers --------------------------------------------------
__device__ __forceinline__ float sigf(float x) {
    return __fdividef(1.0f, 1.0f + __expf(-x));
}
__device__ __forceinline__ float spf(float x) {  // softplus, stable
    return fmaxf(x, 0.0f) + __logf(1.0f + __expf(-fabsf(x)));
}
__device__ __forceinline__ void split_bf16(float x, __nv_bfloat16& hi, __nv_bfloat16& lo) {
    hi = __float2bfloat16_rn(x);
    lo = __float2bfloat16_rn(x - __bfloat162float(hi));
}
__device__ __forceinline__ void mma_bf16(float c[4], uint32_t a0, uint32_t a1,
                                         uint32_t a2, uint32_t a3,
                                         uint32_t b0, uint32_t b1) {
    asm volatile(
        "mma.sync.aligned.m16n8k16.row.col.f32.bf16.bf16.f32 "
        "{%0,%1,%2,%3}, {%4,%5,%6,%7}, {%8,%9}, {%0,%1,%2,%3};\n"
        : "+f"(c[0]), "+f"(c[1]), "+f"(c[2]), "+f"(c[3])
        : "r"(a0), "r"(a1), "r"(a2), "r"(a3), "r"(b0), "r"(b1));
}
__device__ __forceinline__ void ldsm_x4(uint32_t& r0, uint32_t& r1, uint32_t& r2,
                                        uint32_t& r3, uint32_t addr) {
    asm volatile("ldmatrix.sync.aligned.m8n8.x4.shared.b16 {%0,%1,%2,%3}, [%4];"
                 : "=r"(r0), "=r"(r1), "=r"(r2), "=r"(r3) : "r"(addr));
}
__device__ __forceinline__ void ldsm_x2(uint32_t& r0, uint32_t& r1, uint32_t addr) {
    asm volatile("ldmatrix.sync.aligned.m8n8.x2.shared.b16 {%0,%1}, [%2];"
                 : "=r"(r0), "=r"(r1) : "r"(addr));
}
__device__ __forceinline__ uint32_t smem_u32(const void* p) {
    return (uint32_t)__cvta_generic_to_shared(p);
}

// ---------------- repack Wf/Ws into bf16-split TRANSPOSED [4][512][128] -----
// n:  [0,128) f_dst | [128,256) s_dst | [256,384) f_src | [384,512) s_src
__global__ void repack_kernel(const float* __restrict__ Wf, const float* __restrict__ Ws) {
    int idx = blockIdx.x * blockDim.x + threadIdx.x;
    const int total = 4 * 512 * HID;
    if (idx >= total) return;
    int l   = idx / (512 * HID);
    int rem = idx - l * (512 * HID);
    int n   = rem >> 7;     // 0..511
    int k   = rem & 127;    // 0..127
    const float* Wfl = Wf + (size_t)l * 272 * HID;
    const float* Wsl = Ws + (size_t)l * 272 * HID;
    float v;
    if      (n < 128) v = Wfl[k * HID + n];
    else if (n < 256) v = Wsl[k * HID + (n - 128)];
    else if (n < 384) v = Wfl[(128 + k) * HID + (n - 256)];
    else              v = Wsl[(128 + k) * HID + (n - 384)];
    __nv_bfloat16 hi, lo;
    split_bf16(v, hi, lo);
    g_Whi[idx] = hi;
    g_Wlo[idx] = lo;
}

// ---------------- node embedding: h = x @ W_node + b ------------------------
__global__ void embed_kernel(const float* __restrict__ x, const float* __restrict__ Wn,
                             const float* __restrict__ bnode) {
    int gw   = (blockIdx.x * blockDim.x + threadIdx.x) >> 5;
    int lane = threadIdx.x & 31;
    if (gw >= NN) return;
    int j = lane * 4;
    float a[4] = {bnode[j], bnode[j + 1], bnode[j + 2], bnode[j + 3]};
    const float* xr = x + (size_t)gw * 6;
#pragma unroll
    for (int k = 0; k < 6; k++) {
        float xv = xr[k];
        const float* w = Wn + k * HID + j;
        a[0] += xv * w[0]; a[1] += xv * w[1]; a[2] += xv * w[2]; a[3] += xv * w[3];
    }
    *(float4*)(g_h + (size_t)gw * HID + j) = make_float4(a[0], a[1], a[2], a[3]);
#pragma unroll
    for (int t = 0; t < 4; t++) {
        __nv_bfloat16 hi, lo;
        split_bf16(a[t], hi, lo);
        g_hhi[(size_t)gw * HID + j + t] = hi;
        g_hlo[(size_t)gw * HID + j + t] = lo;
    }
}

// ---------------- CSR build --------------------------------------------------
__global__ void csr_zero_kernel() {
    int i = blockIdx.x * blockDim.x + threadIdx.x;
    if (i < NN) g_cnt[i] = 0;
}
__global__ void csr_count_kernel(const int* __restrict__ ei) {
    int e = blockIdx.x * blockDim.x + threadIdx.x;
    if (e < EE) atomicAdd(&g_cnt[ei[EE + e]], 1);
}
__global__ void csr_scan_kernel() {  // single block, 1024 threads
    __shared__ int sums[1024];
    int t = threadIdx.x;
    const int PER = (NN + 1023) / 1024;  // 20
    int base = t * PER;
    int s = 0;
    for (int i = 0; i < PER; i++) {
        int idx = base + i;
        if (idx < NN) s += g_cnt[idx];
    }
    sums[t] = s;
    __syncthreads();
    for (int o = 1; o < 1024; o <<= 1) {
        int v = (t >= o) ? sums[t - o] : 0;
        __syncthreads();
        sums[t] += v;
        __syncthreads();
    }
    int run = sums[t] - s;  // exclusive prefix
    for (int i = 0; i < PER; i++) {
        int idx = base + i;
        if (idx < NN) {
            g_cursor[idx] = run;
            run += g_cnt[idx];
        }
    }
}
__global__ void csr_scatter_kernel(const int* __restrict__ ei, const float* __restrict__ dist) {
    int e = blockIdx.x * blockDim.x + threadIdx.x;
    if (e >= EE) return;
    int src = ei[e];
    int dst = ei[EE + e];
    int pos = atomicAdd(&g_cursor[dst], 1);
    g_esrc[pos]  = src;
    g_edst[pos]  = dst;
    g_edist[pos] = dist[e];
}

// ---------------- tensor-core GEMM: P = h @ W[l]^T, full-K-resident ----------
__global__ __launch_bounds__(512)
void gemm_kernel(int layer, const float* __restrict__ bf_, const float* __restrict__ bs_) {
    extern __shared__ __align__(16) char smem_raw[];
    __nv_bfloat16* Ah = (__nv_bfloat16*)smem_raw;          // [128][ASTR]
    __nv_bfloat16* Al = Ah + 128 * ASTR;
    __nv_bfloat16* Bh = Al + 128 * ASTR;                   // [128 n][ASTR k]
    __nv_bfloat16* Bl = Bh + 128 * ASTR;

    const __nv_bfloat16* Wh = g_Whi + (size_t)layer * 512 * HID;
    const __nv_bfloat16* Wl = g_Wlo + (size_t)layer * 512 * HID;
    int bm = blockIdx.x * 128, bn = blockIdx.y * 128;
    int tid = threadIdx.x;

#pragma unroll
    for (int r = 0; r < 4; r++) {
        int idx = tid + r * 512;          // 0..2047
        int row = idx >> 4, c8 = (idx & 15) * 8;
        int gm = bm + row;
        uint4 vh = make_uint4(0u, 0u, 0u, 0u), vl = vh;
        if (gm < NN) {
            vh = *(const uint4*)&g_hhi[(size_t)gm * HID + c8];
            vl = *(const uint4*)&g_hlo[(size_t)gm * HID + c8];
        }
        *(uint4*)&Ah[row * ASTR + c8] = vh;
        *(uint4*)&Al[row * ASTR + c8] = vl;
    }
#pragma unroll
    for (int r = 0; r < 4; r++) {
        int idx = tid + r * 512;
        int row = idx >> 4, c8 = (idx & 15) * 8;
        *(uint4*)&Bh[row * ASTR + c8] = *(const uint4*)&Wh[(size_t)(bn + row) * HID + c8];
        *(uint4*)&Bl[row * ASTR + c8] = *(const uint4*)&Wl[(size_t)(bn + row) * HID + c8];
    }
    __syncthreads();

    int warp = tid >> 5, lane = tid & 31;
    int wm = (warp >> 2) * 32, wn = (warp & 3) * 32;

    float acc[2][4][4];
#pragma unroll
    for (int mi = 0; mi < 2; mi++)
#pragma unroll
        for (int nj = 0; nj < 4; nj++)
#pragma unroll
            for (int t = 0; t < 4; t++) acc[mi][nj][t] = 0.0f;

    uint32_t aBase = smem_u32(Ah), bBase = smem_u32(Bh);
    const uint32_t HILO_A = (uint32_t)(128 * ASTR * 2);
    int arow = wm + (lane & 15);
    int akof = (lane >> 4) * 8;
    int brow = wn + (lane & 7);
    int bkof = ((lane >> 3) & 1) * 8;

#pragma unroll
    for (int ks = 0; ks < 8; ks++) {
        int k0 = ks * 16;
        uint32_t ah[2][4], al[2][4], bh[4][2], bl[4][2];
#pragma unroll
        for (int mi = 0; mi < 2; mi++) {
            uint32_t ad = aBase + (uint32_t)(((arow + mi * 16) * ASTR + k0 + akof) * 2);
            ldsm_x4(ah[mi][0], ah[mi][1], ah[mi][2], ah[mi][3], ad);
            ldsm_x4(al[mi][0], al[mi][1], al[mi][2], al[mi][3], ad + HILO_A);
        }
#pragma unroll
        for (int nj = 0; nj < 4; nj++) {
            uint32_t bd = bBase + (uint32_t)(((brow + nj * 8) * ASTR + k0 + bkof) * 2);
            ldsm_x2(bh[nj][0], bh[nj][1], bd);
            ldsm_x2(bl[nj][0], bl[nj][1], bd + HILO_A);
        }
#pragma unroll
        for (int mi = 0; mi < 2; mi++)
#pragma unroll
            for (int nj = 0; nj < 4; nj++) {
                mma_bf16(acc[mi][nj], ah[mi][0], ah[mi][1], ah[mi][2], ah[mi][3],
                         bh[nj][0], bh[nj][1]);
                mma_bf16(acc[mi][nj], ah[mi][0], ah[mi][1], ah[mi][2], ah[mi][3],
                         bl[nj][0], bl[nj][1]);
                mma_bf16(acc[mi][nj], al[mi][0], al[mi][1], al[mi][2], al[mi][3],
                         bh[nj][0], bh[nj][1]);
            }
    }

    if (blockIdx.x == 0 && blockIdx.y == 0 && tid < HID) {
        g_cs[tid] = 0.0f;
        g_cq[tid] = 0.0f;
    }

    const float* bptr = (bn == 0) ? bf_ : ((bn == 128) ? bs_ : (const float*)0);
    int crow = lane >> 2, ccol = (lane & 3) * 2;
#pragma unroll
    for (int mi = 0; mi < 2; mi++) {
        int gm0 = bm + wm + mi * 16 + crow;
#pragma unroll
        for (int nj = 0; nj < 4; nj++) {
            int lcol = wn + nj * 8 + ccol;
            float b0 = bptr ? bptr[lcol] : 0.0f;
            float b1 = bptr ? bptr[lcol + 1] : 0.0f;
            int gn = bn + lcol;
            if (gm0 < NN) {
                float2 v = make_float2(acc[mi][nj][0] + b0, acc[mi][nj][1] + b1);
                *(float2*)&g_P[(size_t)gm0 * 512 + gn] = v;
            }
            if (gm0 + 8 < NN) {
                float2 v = make_float2(acc[mi][nj][2] + b0, acc[mi][nj][3] + b1);
                *(float2*)&g_P[(size_t)(gm0 + 8) * 512 + gn] = v;
            }
        }
    }
}

// ---------------- zero agg ----------------------------------------------------
__global__ void zero_kernel() {
    int i = blockIdx.x * blockDim.x + threadIdx.x;
    int stride = gridDim.x * blockDim.x;
    for (int idx = i; idx < NN * HID; idx += stride) g_agg[idx] = 0.0f;
}

// ---------------- edge kernel: 64 CSR-ordered edges per block (scalar, R8) --
__global__ __launch_bounds__(256, 2)
void edge_kernel(const float* __restrict__ WfE, const float* __restrict__ WsE) {
    __shared__ float W_s[16 * 256];   // [k][0..127]=Wef row k, [128..255]=Wes row k
    __shared__ float E_s[64 * 17];    // per-edge RBF values
    __shared__ float s_dist[64];
    __shared__ int   s_src[64];
    __shared__ int   s_dst[64];
    int tid = threadIdx.x;
    int eb = blockIdx.x * 64;
#pragma unroll
    for (int i = tid; i < 2048; i += 256) {
        int k = i >> 7, j = i & 127;
        W_s[(k << 8) + j]       = WfE[i];
        W_s[(k << 8) + 128 + j] = WsE[i];
    }
    if (tid < 64) {
        int e = eb + tid;
        s_src[tid]  = g_esrc[e];
        s_dst[tid]  = g_edst[e];
        s_dist[tid] = g_edist[e];
    }
    __syncthreads();
#pragma unroll
    for (int i = tid; i < 1024; i += 256) {
        int le = i >> 4, k = i & 15;
        float t = s_dist[le] - (float)k * RBF_S;
        E_s[le * 17 + k] = __expf(RBF_C * t * t);
    }
    __syncthreads();

    int c = tid & 31, g = tid >> 5;
    int j4 = c * 4;
    float acc[8][8];
#pragma unroll
    for (int i = 0; i < 8; i++)
#pragma unroll
        for (int j = 0; j < 8; j++) acc[i][j] = 0.0f;

#pragma unroll
    for (int k = 0; k < 16; k++) {
        float4 wf = *(const float4*)&W_s[(k << 8) + j4];
        float4 ws = *(const float4*)&W_s[(k << 8) + 128 + j4];
#pragma unroll
        for (int i = 0; i < 8; i++) {
            float a = E_s[(g * 8 + i) * 17 + k];
            acc[i][0] += a * wf.x; acc[i][1] += a * wf.y;
            acc[i][2] += a * wf.z; acc[i][3] += a * wf.w;
            acc[i][4] += a * ws.x; acc[i][5] += a * ws.y;
            acc[i][6] += a * ws.z; acc[i][7] += a * ws.w;
        }
    }

    // epilogue: gather P (dst rows cached across the CSR run), activations,
    // run-length accumulate by dst
    int cur = -1, prevdst = -1;
    float m0 = 0.f, m1 = 0.f, m2 = 0.f, m3 = 0.f;
    float4 fd = make_float4(0.f, 0.f, 0.f, 0.f), sd = fd;
#pragma unroll
    for (int i = 0; i < 8; i++) {
        int le = g * 8 + i;
        int src = s_src[le], dst = s_dst[le];
        if (dst != prevdst) {
            const float* pd = g_P + (size_t)dst * 512;
            fd = *(const float4*)(pd + j4);
            sd = *(const float4*)(pd + 128 + j4);
            prevdst = dst;
        }
        const float* ps = g_P + (size_t)src * 512;
        float4 fs = *(const float4*)(ps + 256 + j4);
        float4 ss = *(const float4*)(ps + 384 + j4);
        float f0 = acc[i][0] + fd.x + fs.x;
        float f1 = acc[i][1] + fd.y + fs.y;
        float f2 = acc[i][2] + fd.z + fs.z;
        float f3 = acc[i][3] + fd.w + fs.w;
        float s0 = acc[i][4] + sd.x + ss.x;
        float s1 = acc[i][5] + sd.y + ss.y;
        float s2 = acc[i][6] + sd.z + ss.z;
        float s3 = acc[i][7] + sd.w + ss.w;
        float q0 = sigf(f0) * spf(s0);
        float q1 = sigf(f1) * spf(s1);
        float q2 = sigf(f2) * spf(s2);
        float q3 = sigf(f3) * spf(s3);
        if (dst != cur) {
            if (cur >= 0) {
                float* ap = g_agg + (size_t)cur * HID + j4;
                atomicAdd(ap + 0, m0); atomicAdd(ap + 1, m1);
                atomicAdd(ap + 2, m2); atomicAdd(ap + 3, m3);
            }
            cur = dst;
            m0 = q0; m1 = q1; m2 = q2; m3 = q3;
        } else {
            m0 += q0; m1 += q1; m2 += q2; m3 += q3;
        }
    }
    if (cur >= 0) {
        float* ap = g_agg + (size_t)cur * HID + j4;
        atomicAdd(ap + 0, m0); atomicAdd(ap + 1, m1);
        atomicAdd(ap + 2, m2); atomicAdd(ap + 3, m3);
    }
}

// ---------------- BN column stats -------------------------------------------
__global__ void bnstats_kernel() {
    int jj = threadIdx.x;  // 128 threads
    float s = 0.0f, q = 0.0f;
    for (int r = blockIdx.x; r < NN; r += gridDim.x) {
        float v = g_agg[(size_t)r * HID + jj];
        s += v;
        q += v * v;
    }
    atomicAdd(&g_cs[jj], s);
    atomicAdd(&g_cq[jj], q);
}

// ---------------- fused BN + residual + LN + ReLU + residual ----------------
__global__ void update_kernel(const float* __restrict__ bng, const float* __restrict__ bnb,
                              const float* __restrict__ lng, const float* __restrict__ lnb) {
    int gw   = (blockIdx.x * blockDim.x + threadIdx.x) >> 5;
    int lane = threadIdx.x & 31;
    if (gw >= NN) return;
    int j = lane * 4;
    float4 a  = *(const float4*)(g_agg + (size_t)gw * HID + j);
    float4 hv = *(const float4*)(g_h   + (size_t)gw * HID + j);
    float4 cs = *(const float4*)(g_cs + j);
    float4 cq = *(const float4*)(g_cq + j);
    float4 gg = *(const float4*)(bng + j);
    float4 bb = *(const float4*)(bnb + j);
    const float invN = 1.0f / (float)NN;
    float av[4]  = {a.x, a.y, a.z, a.w};
    float hh[4]  = {hv.x, hv.y, hv.z, hv.w};
    float csv[4] = {cs.x, cs.y, cs.z, cs.w};
    float cqv[4] = {cq.x, cq.y, cq.z, cq.w};
    float ggv[4] = {gg.x, gg.y, gg.z, gg.w};
    float bbv[4] = {bb.x, bb.y, bb.z, bb.w};
    float cvals[4];
    float sum = 0.0f, sq = 0.0f;
#pragma unroll
    for (int t = 0; t < 4; t++) {
        float mu  = csv[t] * invN;
        float var = cqv[t] * invN - mu * mu;
        float an  = (av[t] - mu) * rsqrtf(var + EPSN) * ggv[t] + bbv[t];
        cvals[t] = an + hh[t];
        sum += cvals[t];
        sq  += cvals[t] * cvals[t];
    }
#pragma unroll
    for (int o = 16; o; o >>= 1) {
        sum += __shfl_xor_sync(0xffffffffu, sum, o);
        sq  += __shfl_xor_sync(0xffffffffu, sq, o);
    }
    float m  = sum * (1.0f / HID);
    float v  = sq * (1.0f / HID) - m * m;
    float rs = rsqrtf(v + EPSN);
    float4 lg = *(const float4*)(lng + j);
    float4 lb = *(const float4*)(lnb + j);
    float lgv[4] = {lg.x, lg.y, lg.z, lg.w};
    float lbv[4] = {lb.x, lb.y, lb.z, lb.w};
    float o4[4];
#pragma unroll
    for (int t = 0; t < 4; t++)
        o4[t] = fmaxf((cvals[t] - m) * rs * lgv[t] + lbv[t], 0.0f) + hh[t];
    *(float4*)(g_h + (size_t)gw * HID + j) = make_float4(o4[0], o4[1], o4[2], o4[3]);
#pragma unroll
    for (int t = 0; t < 4; t++) {
        __nv_bfloat16 hi, lo;
        split_bf16(o4[t], hi, lo);
        g_hhi[(size_t)gw * HID + j + t] = hi;
        g_hlo[(size_t)gw * HID + j + t] = lo;
    }
}

// ---------------- final LN + FC ---------------------------------------------
__global__ void final_kernel(const float* __restrict__ lng, const float* __restrict__ lnb,
                             const float* __restrict__ Wfc, const float* __restrict__ bfc,
                             float* __restrict__ out) {
    int gw   = (blockIdx.x * blockDim.x + threadIdx.x) >> 5;
    int lane = threadIdx.x & 31;
    if (gw >= NN) return;
    int j = lane * 4;
    float4 hv = *(const float4*)(g_h + (size_t)gw * HID + j);
    float hh[4] = {hv.x, hv.y, hv.z, hv.w};
    float sum = hh[0] + hh[1] + hh[2] + hh[3];
    float sq  = hh[0] * hh[0] + hh[1] * hh[1] + hh[2] * hh[2] + hh[3] * hh[3];
#pragma unroll
    for (int o = 16; o; o >>= 1) {
        sum += __shfl_xor_sync(0xffffffffu, sum, o);
        sq  += __shfl_xor_sync(0xffffffffu, sq, o);
    }
    float m  = sum * (1.0f / HID);
    float v  = sq * (1.0f / HID) - m * m;
    float rs = rsqrtf(v + EPSN);
    float4 lg = *(const float4*)(lng + j);
    float4 lb = *(const float4*)(lnb + j);
    float hn[4];
    hn[0] = (hh[0] - m) * rs * lg.x + lb.x;
    hn[1] = (hh[1] - m) * rs * lg.y + lb.y;
    hn[2] = (hh[2] - m) * rs * lg.z + lb.z;
    hn[3] = (hh[3] - m) * rs * lg.w + lb.w;
#pragma unroll
    for (int c = 0; c < NCLS; c++) {
        float p = hn[0] * Wfc[(j + 0) * NCLS + c]
                + hn[1] * Wfc[(j + 1) * NCLS + c]
                + hn[2] * Wfc[(j + 2) * NCLS + c]
                + hn[3] * Wfc[(j + 3) * NCLS + c];
#pragma unroll
        for (int o = 16; o; o >>= 1) p += __shfl_xor_sync(0xffffffffu, p, o);
        if (lane == 0) out[(size_t)gw * NCLS + c] = p + bfc[c];
    }
}

// ---------------- launch (exact R8 ordering) ---------------------------------
extern "C" void kernel_launch(void* const* d_in, const int* in_sizes, int n_in,
                              void* d_out, int out_size) {
    const float* x    = (const float*)d_in[0];
    const int*   ei   = (const int*)d_in[1];
    const float* dist = (const float*)d_in[2];
    const float* Wn   = (const float*)d_in[3];
    const float* bnd  = (const float*)d_in[4];
    const float* Wf   = (const float*)d_in[5];
    const float* bf   = (const float*)d_in[6];
    const float* Ws   = (const float*)d_in[7];
    const float* bs   = (const float*)d_in[8];
    const float* bng  = (const float*)d_in[9];
    const float* bnb  = (const float*)d_in[10];
    const float* lng  = (const float*)d_in[11];
    const float* lnb  = (const float*)d_in[12];
    const float* lgo  = (const float*)d_in[13];
    const float* lbo  = (const float*)d_in[14];
    const float* Wfc  = (const float*)d_in[15];
    const float* bfc  = (const float*)d_in[16];
    float* out = (float*)d_out;

    cudaFuncSetAttribute(gemm_kernel, cudaFuncAttributeMaxDynamicSharedMemorySize,
                         GEMM_SMEM);

    repack_kernel<<<(4 * 512 * HID + 255) / 256, 256>>>(Wf, Ws);
    embed_kernel<<<(NN * 32 + 255) / 256, 256>>>(x, Wn, bnd);
    csr_zero_kernel<<<(NN + 255) / 256, 256>>>();
    csr_count_kernel<<<(EE + 255) / 256, 256>>>(ei);
    csr_scan_kernel<<<1, 1024>>>();
    csr_scatter_kernel<<<(EE + 255) / 256, 256>>>(ei, dist);

    for (int l = 0; l < 4; l++) {
        dim3 gg((NN + 127) / 128, 512 / 128);
        gemm_kernel<<<gg, 512, GEMM_SMEM>>>(l, bf + l * HID, bs + l * HID);
        zero_kernel<<<512, 256>>>();
        edge_kernel<<<EE / 64, 256>>>(Wf + (size_t)l * 272 * HID + 256 * HID,
                                      Ws + (size_t)l * 272 * HID + 256 * HID);
        bnstats_kernel<<<512, HID>>>();
        update_kernel<<<(NN * 32 + 255) / 256, 256>>>(bng + l * HID, bnb + l * HID,
                                                      lng + l * HID, lnb + l * HID);
    }
    final_kernel<<<(NN * 32 + 255) / 256, 256>>>(lgo, lbo, Wfc, bfc, out);
}

// round 12
// speedup vs baseline: 1.5521x; 1.0491x over previous
#include <cuda_runtime.h>
#include <cuda_bf16.h>
#include <cstdint>

#define NN   20000
#define EE   320000
#define HID  128
#define NCLS 21
#define EPSN 1e-5f
#define RBF_C (-1.7578125f)          /* -0.5/(8/15)^2 */
#define RBF_S (0.53333333333333333f) /* 8/15 */
#define ASTR 136                      /* padded bf16 row stride in smem tiles */
#define GEMM_SMEM (4 * 128 * ASTR * 2)

// ---------------- scratch (device globals; no allocation allowed) ----------
__device__ float g_h  [(size_t)NN * HID];   // node features (fp32)
__device__ __nv_bfloat16 g_hhi[(size_t)NN * HID];  // bf16 split of h
__device__ __nv_bfloat16 g_hlo[(size_t)NN * HID];
__device__ float g_P  [(size_t)NN * 512];   // per-node proj [f_dst|s_dst|f_src|s_src]
__device__ float g_agg[(size_t)NN * HID];   // aggregated messages
__device__ __nv_bfloat16 g_Whi[4 * 512 * HID];  // W transposed [l][n=512][k=128]
__device__ __nv_bfloat16 g_Wlo[4 * 512 * HID];
__device__ float g_cs [HID];                // BN column sums
__device__ float g_cq [HID];                // BN column sumsqs
// CSR scratch
__device__ int   g_cnt   [NN];
__device__ int   g_cursor[NN];
__device__ int   g_esrc  [EE];
__device__ int   g_edst  [EE];
__device__ float g_edist [EE];

// ---------------- helpers --------------------------------------------------
__device__ __forceinline__ float sigf(float x) {
    return __fdividef(1.0f, 1.0f + __expf(-x));
}
__device__ __forceinline__ float spf(float x) {  // softplus, stable
    return fmaxf(x, 0.0f) + __logf(1.0f + __expf(-fabsf(x)));
}
__device__ __forceinline__ void split_bf16(float x, __nv_bfloat16& hi, __nv_bfloat16& lo) {
    hi = __float2bfloat16_rn(x);
    lo = __float2bfloat16_rn(x - __bfloat162float(hi));
}
__device__ __forceinline__ void mma_bf16(float c[4], uint32_t a0, uint32_t a1,
                                         uint32_t a2, uint32_t a3,
                                         uint32_t b0, uint32_t b1) {
    asm volatile(
        "mma.sync.aligned.m16n8k16.row.col.f32.bf16.bf16.f32 "
        "{%0,%1,%2,%3}, {%4,%5,%6,%7}, {%8,%9}, {%0,%1,%2,%3};\n"
        : "+f"(c[0]), "+f"(c[1]), "+f"(c[2]), "+f"(c[3])
        : "r"(a0), "r"(a1), "r"(a2), "r"(a3), "r"(b0), "r"(b1));
}
__device__ __forceinline__ void ldsm_x4(uint32_t& r0, uint32_t& r1, uint32_t& r2,
                                        uint32_t& r3, uint32_t addr) {
    asm volatile("ldmatrix.sync.aligned.m8n8.x4.shared.b16 {%0,%1,%2,%3}, [%4];"
                 : "=r"(r0), "=r"(r1), "=r"(r2), "=r"(r3) : "r"(addr));
}
__device__ __forceinline__ void ldsm_x2(uint32_t& r0, uint32_t& r1, uint32_t addr) {
    asm volatile("ldmatrix.sync.aligned.m8n8.x2.shared.b16 {%0,%1}, [%2];"
                 : "=r"(r0), "=r"(r1) : "r"(addr));
}
__device__ __forceinline__ uint32_t smem_u32(const void* p) {
    return (uint32_t)__cvta_generic_to_shared(p);
}

// ---------------- repack Wf/Ws into bf16-split TRANSPOSED [4][512][128] -----
// n:  [0,128) f_dst | [128,256) s_dst | [256,384) f_src | [384,512) s_src
__global__ void repack_kernel(const float* __restrict__ Wf, const float* __restrict__ Ws) {
    int idx = blockIdx.x * blockDim.x + threadIdx.x;
    const int total = 4 * 512 * HID;
    if (idx >= total) return;
    int l   = idx / (512 * HID);
    int rem = idx - l * (512 * HID);
    int n   = rem >> 7;     // 0..511
    int k   = rem & 127;    // 0..127
    const float* Wfl = Wf + (size_t)l * 272 * HID;
    const float* Wsl = Ws + (size_t)l * 272 * HID;
    float v;
    if      (n < 128) v = Wfl[k * HID + n];
    else if (n < 256) v = Wsl[k * HID + (n - 128)];
    else if (n < 384) v = Wfl[(128 + k) * HID + (n - 256)];
    else              v = Wsl[(128 + k) * HID + (n - 384)];
    __nv_bfloat16 hi, lo;
    split_bf16(v, hi, lo);
    g_Whi[idx] = hi;
    g_Wlo[idx] = lo;
}

// ---------------- node embedding: h = x @ W_node + b ------------------------
__global__ void embed_kernel(const float* __restrict__ x, const float* __restrict__ Wn,
                             const float* __restrict__ bnode) {
    int gw   = (blockIdx.x * blockDim.x + threadIdx.x) >> 5;
    int lane = threadIdx.x & 31;
    if (gw >= NN) return;
    int j = lane * 4;
    float a[4] = {bnode[j], bnode[j + 1], bnode[j + 2], bnode[j + 3]};
    const float* xr = x + (size_t)gw * 6;
#pragma unroll
    for (int k = 0; k < 6; k++) {
        float xv = xr[k];
        const float* w = Wn + k * HID + j;
        a[0] += xv * w[0]; a[1] += xv * w[1]; a[2] += xv * w[2]; a[3] += xv * w[3];
    }
    *(float4*)(g_h + (size_t)gw * HID + j) = make_float4(a[0], a[1], a[2], a[3]);
#pragma unroll
    for (int t = 0; t < 4; t++) {
        __nv_bfloat16 hi, lo;
        split_bf16(a[t], hi, lo);
        g_hhi[(size_t)gw * HID + j + t] = hi;
        g_hlo[(size_t)gw * HID + j + t] = lo;
    }
}

// ---------------- CSR build --------------------------------------------------
__global__ void csr_zero_kernel() {
    int i = blockIdx.x * blockDim.x + threadIdx.x;
    if (i < NN) g_cnt[i] = 0;
}
__global__ void csr_count_kernel(const int* __restrict__ ei) {
    int e = blockIdx.x * blockDim.x + threadIdx.x;
    if (e < EE) atomicAdd(&g_cnt[ei[EE + e]], 1);
}
__global__ void csr_scan_kernel() {  // single block, 1024 threads
    __shared__ int sums[1024];
    int t = threadIdx.x;
    const int PER = (NN + 1023) / 1024;  // 20
    int base = t * PER;
    int s = 0;
    for (int i = 0; i < PER; i++) {
        int idx = base + i;
        if (idx < NN) s += g_cnt[idx];
    }
    sums[t] = s;
    __syncthreads();
    for (int o = 1; o < 1024; o <<= 1) {
        int v = (t >= o) ? sums[t - o] : 0;
        __syncthreads();
        sums[t] += v;
        __syncthreads();
    }
    int run = sums[t] - s;  // exclusive prefix
    for (int i = 0; i < PER; i++) {
        int idx = base + i;
        if (idx < NN) {
            g_cursor[idx] = run;
            run += g_cnt[idx];
        }
    }
}
__global__ void csr_scatter_kernel(const int* __restrict__ ei, const float* __restrict__ dist) {
    int e = blockIdx.x * blockDim.x + threadIdx.x;
    if (e >= EE) return;
    int src = ei[e];
    int dst = ei[EE + e];
    int pos = atomicAdd(&g_cursor[dst], 1);
    g_esrc[pos]  = src;
    g_edst[pos]  = dst;
    g_edist[pos] = dist[e];
}

// ---------------- tensor-core GEMM: P = h @ W[l]^T, full-K-resident ----------
__global__ __launch_bounds__(512)
void gemm_kernel(int layer, const float* __restrict__ bf_, const float* __restrict__ bs_) {
    extern __shared__ __align__(16) char smem_raw[];
    __nv_bfloat16* Ah = (__nv_bfloat16*)smem_raw;          // [128][ASTR]
    __nv_bfloat16* Al = Ah + 128 * ASTR;
    __nv_bfloat16* Bh = Al + 128 * ASTR;                   // [128 n][ASTR k]
    __nv_bfloat16* Bl = Bh + 128 * ASTR;

    const __nv_bfloat16* Wh = g_Whi + (size_t)layer * 512 * HID;
    const __nv_bfloat16* Wl = g_Wlo + (size_t)layer * 512 * HID;
    int bm = blockIdx.x * 128, bn = blockIdx.y * 128;
    int tid = threadIdx.x;

#pragma unroll
    for (int r = 0; r < 4; r++) {
        int idx = tid + r * 512;          // 0..2047
        int row = idx >> 4, c8 = (idx & 15) * 8;
        int gm = bm + row;
        uint4 vh = make_uint4(0u, 0u, 0u, 0u), vl = vh;
        if (gm < NN) {
            vh = *(const uint4*)&g_hhi[(size_t)gm * HID + c8];
            vl = *(const uint4*)&g_hlo[(size_t)gm * HID + c8];
        }
        *(uint4*)&Ah[row * ASTR + c8] = vh;
        *(uint4*)&Al[row * ASTR + c8] = vl;
    }
#pragma unroll
    for (int r = 0; r < 4; r++) {
        int idx = tid + r * 512;
        int row = idx >> 4, c8 = (idx & 15) * 8;
        *(uint4*)&Bh[row * ASTR + c8] = *(const uint4*)&Wh[(size_t)(bn + row) * HID + c8];
        *(uint4*)&Bl[row * ASTR + c8] = *(const uint4*)&Wl[(size_t)(bn + row) * HID + c8];
    }
    __syncthreads();

    int warp = tid >> 5, lane = tid & 31;
    int wm = (warp >> 2) * 32, wn = (warp & 3) * 32;

    float acc[2][4][4];
#pragma unroll
    for (int mi = 0; mi < 2; mi++)
#pragma unroll
        for (int nj = 0; nj < 4; nj++)
#pragma unroll
            for (int t = 0; t < 4; t++) acc[mi][nj][t] = 0.0f;

    uint32_t aBase = smem_u32(Ah), bBase = smem_u32(Bh);
    const uint32_t HILO_A = (uint32_t)(128 * ASTR * 2);
    int arow = wm + (lane & 15);
    int akof = (lane >> 4) * 8;
    int brow = wn + (lane & 7);
    int bkof = ((lane >> 3) & 1) * 8;

#pragma unroll
    for (int ks = 0; ks < 8; ks++) {
        int k0 = ks * 16;
        uint32_t ah[2][4], al[2][4], bh[4][2], bl[4][2];
#pragma unroll
        for (int mi = 0; mi < 2; mi++) {
            uint32_t ad = aBase + (uint32_t)(((arow + mi * 16) * ASTR + k0 + akof) * 2);
            ldsm_x4(ah[mi][0], ah[mi][1], ah[mi][2], ah[mi][3], ad);
            ldsm_x4(al[mi][0], al[mi][1], al[mi][2], al[mi][3], ad + HILO_A);
        }
#pragma unroll
        for (int nj = 0; nj < 4; nj++) {
            uint32_t bd = bBase + (uint32_t)(((brow + nj * 8) * ASTR + k0 + bkof) * 2);
            ldsm_x2(bh[nj][0], bh[nj][1], bd);
            ldsm_x2(bl[nj][0], bl[nj][1], bd + HILO_A);
        }
#pragma unroll
        for (int mi = 0; mi < 2; mi++)
#pragma unroll
            for (int nj = 0; nj < 4; nj++) {
                mma_bf16(acc[mi][nj], ah[mi][0], ah[mi][1], ah[mi][2], ah[mi][3],
                         bh[nj][0], bh[nj][1]);
                mma_bf16(acc[mi][nj], ah[mi][0], ah[mi][1], ah[mi][2], ah[mi][3],
                         bl[nj][0], bl[nj][1]);
                mma_bf16(acc[mi][nj], al[mi][0], al[mi][1], al[mi][2], al[mi][3],
                         bh[nj][0], bh[nj][1]);
            }
    }

    if (blockIdx.x == 0 && blockIdx.y == 0 && tid < HID) {
        g_cs[tid] = 0.0f;
        g_cq[tid] = 0.0f;
    }

    const float* bptr = (bn == 0) ? bf_ : ((bn == 128) ? bs_ : (const float*)0);
    int crow = lane >> 2, ccol = (lane & 3) * 2;
#pragma unroll
    for (int mi = 0; mi < 2; mi++) {
        int gm0 = bm + wm + mi * 16 + crow;
#pragma unroll
        for (int nj = 0; nj < 4; nj++) {
            int lcol = wn + nj * 8 + ccol;
            float b0 = bptr ? bptr[lcol] : 0.0f;
            float b1 = bptr ? bptr[lcol + 1] : 0.0f;
            int gn = bn + lcol;
            if (gm0 < NN) {
                float2 v = make_float2(acc[mi][nj][0] + b0, acc[mi][nj][1] + b1);
                *(float2*)&g_P[(size_t)gm0 * 512 + gn] = v;
            }
            if (gm0 + 8 < NN) {
                float2 v = make_float2(acc[mi][nj][2] + b0, acc[mi][nj][3] + b1);
                *(float2*)&g_P[(size_t)(gm0 + 8) * 512 + gn] = v;
            }
        }
    }
}

// ---------------- zero agg (once, before layer 0) ----------------------------
__global__ void zero_kernel() {
    int i = blockIdx.x * blockDim.x + threadIdx.x;
    int stride = gridDim.x * blockDim.x;
    for (int idx = i; idx < NN * HID; idx += stride) g_agg[idx] = 0.0f;
}

// ---------------- edge kernel: 128 CSR-ordered edges per block (2 halves) ---
__global__ __launch_bounds__(256, 2)
void edge_kernel(const float* __restrict__ WfE, const float* __restrict__ WsE) {
    __shared__ float W_s[16 * 256];    // [k][0..127]=Wef row k, [128..255]=Wes row k
    __shared__ float E_s[128 * 17];    // per-edge RBF values
    __shared__ float s_dist[128];
    __shared__ int   s_src[128];
    __shared__ int   s_dst[128];
    int tid = threadIdx.x;
    int eb = blockIdx.x * 128;
#pragma unroll
    for (int i = tid; i < 2048; i += 256) {
        int k = i >> 7, j = i & 127;
        W_s[(k << 8) + j]       = WfE[i];
        W_s[(k << 8) + 128 + j] = WsE[i];
    }
    if (tid < 128) {
        int e = eb + tid;
        s_src[tid]  = g_esrc[e];
        s_dst[tid]  = g_edst[e];
        s_dist[tid] = g_edist[e];
    }
    __syncthreads();
#pragma unroll
    for (int i = tid; i < 2048; i += 256) {
        int le = i >> 4, k = i & 15;
        float t = s_dist[le] - (float)k * RBF_S;
        E_s[le * 17 + k] = __expf(RBF_C * t * t);
    }
    __syncthreads();

    int c = tid & 31, g = tid >> 5;
    int j4 = c * 4;

#pragma unroll
    for (int h = 0; h < 2; h++) {
        float acc[8][8];
#pragma unroll
        for (int i = 0; i < 8; i++)
#pragma unroll
            for (int j = 0; j < 8; j++) acc[i][j] = 0.0f;

#pragma unroll
        for (int k = 0; k < 16; k++) {
            float4 wf = *(const float4*)&W_s[(k << 8) + j4];
            float4 ws = *(const float4*)&W_s[(k << 8) + 128 + j4];
#pragma unroll
            for (int i = 0; i < 8; i++) {
                float a = E_s[(h * 64 + g * 8 + i) * 17 + k];
                acc[i][0] += a * wf.x; acc[i][1] += a * wf.y;
                acc[i][2] += a * wf.z; acc[i][3] += a * wf.w;
                acc[i][4] += a * ws.x; acc[i][5] += a * ws.y;
                acc[i][6] += a * ws.z; acc[i][7] += a * ws.w;
            }
        }

        // epilogue: gather P (dst rows cached), activations, run-length atomics
        int cur = -1, prevdst = -1;
        float m0 = 0.f, m1 = 0.f, m2 = 0.f, m3 = 0.f;
        float4 fd = make_float4(0.f, 0.f, 0.f, 0.f), sd = fd;
#pragma unroll
        for (int i = 0; i < 8; i++) {
            int le = h * 64 + g * 8 + i;
            int src = s_src[le], dst = s_dst[le];
            if (dst != prevdst) {
                const float* pd = g_P + (size_t)dst * 512;
                fd = *(const float4*)(pd + j4);
                sd = *(const float4*)(pd + 128 + j4);
                prevdst = dst;
            }
            const float* ps = g_P + (size_t)src * 512;
            float4 fs = *(const float4*)(ps + 256 + j4);
            float4 ss = *(const float4*)(ps + 384 + j4);
            float f0 = acc[i][0] + fd.x + fs.x;
            float f1 = acc[i][1] + fd.y + fs.y;
            float f2 = acc[i][2] + fd.z + fs.z;
            float f3 = acc[i][3] + fd.w + fs.w;
            float s0 = acc[i][4] + sd.x + ss.x;
            float s1 = acc[i][5] + sd.y + ss.y;
            float s2 = acc[i][6] + sd.z + ss.z;
            float s3 = acc[i][7] + sd.w + ss.w;
            float q0 = sigf(f0) * spf(s0);
            float q1 = sigf(f1) * spf(s1);
            float q2 = sigf(f2) * spf(s2);
            float q3 = sigf(f3) * spf(s3);
            if (dst != cur) {
                if (cur >= 0) {
                    float* ap = g_agg + (size_t)cur * HID + j4;
                    atomicAdd(ap + 0, m0); atomicAdd(ap + 1, m1);
                    atomicAdd(ap + 2, m2); atomicAdd(ap + 3, m3);
                }
                cur = dst;
                m0 = q0; m1 = q1; m2 = q2; m3 = q3;
            } else {
                m0 += q0; m1 += q1; m2 += q2; m3 += q3;
            }
        }
        if (cur >= 0) {
            float* ap = g_agg + (size_t)cur * HID + j4;
            atomicAdd(ap + 0, m0); atomicAdd(ap + 1, m1);
            atomicAdd(ap + 2, m2); atomicAdd(ap + 3, m3);
        }
    }
}

// ---------------- BN column stats -------------------------------------------
__global__ void bnstats_kernel() {
    int jj = threadIdx.x;  // 128 threads
    float s = 0.0f, q = 0.0f;
    for (int r = blockIdx.x; r < NN; r += gridDim.x) {
        float v = g_agg[(size_t)r * HID + jj];
        s += v;
        q += v * v;
    }
    atomicAdd(&g_cs[jj], s);
    atomicAdd(&g_cq[jj], q);
}

// ---------------- fused BN + residual + LN + ReLU + residual + re-zero ------
__global__ void update_kernel(const float* __restrict__ bng, const float* __restrict__ bnb,
                              const float* __restrict__ lng, const float* __restrict__ lnb) {
    int gw   = (blockIdx.x * blockDim.x + threadIdx.x) >> 5;
    int lane = threadIdx.x & 31;
    if (gw >= NN) return;
    int j = lane * 4;
    float4 a  = *(const float4*)(g_agg + (size_t)gw * HID + j);
    float4 hv = *(const float4*)(g_h   + (size_t)gw * HID + j);
    float4 cs = *(const float4*)(g_cs + j);
    float4 cq = *(const float4*)(g_cq + j);
    float4 gg = *(const float4*)(bng + j);
    float4 bb = *(const float4*)(bnb + j);
    // re-zero agg for the next layer (replaces standalone zero_kernel)
    *(float4*)(g_agg + (size_t)gw * HID + j) = make_float4(0.f, 0.f, 0.f, 0.f);
    const float invN = 1.0f / (float)NN;
    float av[4]  = {a.x, a.y, a.z, a.w};
    float hh[4]  = {hv.x, hv.y, hv.z, hv.w};
    float csv[4] = {cs.x, cs.y, cs.z, cs.w};
    float cqv[4] = {cq.x, cq.y, cq.z, cq.w};
    float ggv[4] = {gg.x, gg.y, gg.z, gg.w};
    float bbv[4] = {bb.x, bb.y, bb.z, bb.w};
    float cvals[4];
    float sum = 0.0f, sq = 0.0f;
#pragma unroll
    for (int t = 0; t < 4; t++) {
        float mu  = csv[t] * invN;
        float var = cqv[t] * invN - mu * mu;
        float an  = (av[t] - mu) * rsqrtf(var + EPSN) * ggv[t] + bbv[t];
        cvals[t] = an + hh[t];
        sum += cvals[t];
        sq  += cvals[t] * cvals[t];
    }
#pragma unroll
    for (int o = 16; o; o >>= 1) {
        sum += __shfl_xor_sync(0xffffffffu, sum, o);
        sq  += __shfl_xor_sync(0xffffffffu, sq, o);
    }
    float m  = sum * (1.0f / HID);
    float v  = sq * (1.0f / HID) - m * m;
    float rs = rsqrtf(v + EPSN);
    float4 lg = *(const float4*)(lng + j);
    float4 lb = *(const float4*)(lnb + j);
    float lgv[4] = {lg.x, lg.y, lg.z, lg.w};
    float lbv[4] = {lb.x, lb.y, lb.z, lb.w};
    float o4[4];
#pragma unroll
    for (int t = 0; t < 4; t++)
        o4[t] = fmaxf((cvals[t] - m) * rs * lgv[t] + lbv[t], 0.0f) + hh[t];
    *(float4*)(g_h + (size_t)gw * HID + j) = make_float4(o4[0], o4[1], o4[2], o4[3]);
#pragma unroll
    for (int t = 0; t < 4; t++) {
        __nv_bfloat16 hi, lo;
        split_bf16(o4[t], hi, lo);
        g_hhi[(size_t)gw * HID + j + t] = hi;
        g_hlo[(size_t)gw * HID + j + t] = lo;
    }
}

// ---------------- final LN + FC ---------------------------------------------
__global__ void final_kernel(const float* __restrict__ lng, const float* __restrict__ lnb,
                             const float* __restrict__ Wfc, const float* __restrict__ bfc,
                             float* __restrict__ out) {
    int gw   = (blockIdx.x * blockDim.x + threadIdx.x) >> 5;
    int lane = threadIdx.x & 31;
    if (gw >= NN) return;
    int j = lane * 4;
    float4 hv = *(const float4*)(g_h + (size_t)gw * HID + j);
    float hh[4] = {hv.x, hv.y, hv.z, hv.w};
    float sum = hh[0] + hh[1] + hh[2] + hh[3];
    float sq  = hh[0] * hh[0] + hh[1] * hh[1] + hh[2] * hh[2] + hh[3] * hh[3];
#pragma unroll
    for (int o = 16; o; o >>= 1) {
        sum += __shfl_xor_sync(0xffffffffu, sum, o);
        sq  += __shfl_xor_sync(0xffffffffu, sq, o);
    }
    float m  = sum * (1.0f / HID);
    float v  = sq * (1.0f / HID) - m * m;
    float rs = rsqrtf(v + EPSN);
    float4 lg = *(const float4*)(lng + j);
    float4 lb = *(const float4*)(lnb + j);
    float hn[4];
    hn[0] = (hh[0] - m) * rs * lg.x + lb.x;
    hn[1] = (hh[1] - m) * rs * lg.y + lb.y;
    hn[2] = (hh[2] - m) * rs * lg.z + lb.z;
    hn[3] = (hh[3] - m) * rs * lg.w + lb.w;
#pragma unroll
    for (int c = 0; c < NCLS; c++) {
        float p = hn[0] * Wfc[(j + 0) * NCLS + c]
                + hn[1] * Wfc[(j + 1) * NCLS + c]
                + hn[2] * Wfc[(j + 2) * NCLS + c]
                + hn[3] * Wfc[(j + 3) * NCLS + c];
#pragma unroll
        for (int o = 16; o; o >>= 1) p += __shfl_xor_sync(0xffffffffu, p, o);
        if (lane == 0) out[(size_t)gw * NCLS + c] = p + bfc[c];
    }
}

// ---------------- launch (R11 ordering; zero hoisted before the loop) --------
extern "C" void kernel_launch(void* const* d_in, const int* in_sizes, int n_in,
                              void* d_out, int out_size) {
    const float* x    = (const float*)d_in[0];
    const int*   ei   = (const int*)d_in[1];
    const float* dist = (const float*)d_in[2];
    const float* Wn   = (const float*)d_in[3];
    const float* bnd  = (const float*)d_in[4];
    const float* Wf   = (const float*)d_in[5];
    const float* bf   = (const float*)d_in[6];
    const float* Ws   = (const float*)d_in[7];
    const float* bs   = (const float*)d_in[8];
    const float* bng  = (const float*)d_in[9];
    const float* bnb  = (const float*)d_in[10];
    const float* lng  = (const float*)d_in[11];
    const float* lnb  = (const float*)d_in[12];
    const float* lgo  = (const float*)d_in[13];
    const float* lbo  = (const float*)d_in[14];
    const float* Wfc  = (const float*)d_in[15];
    const float* bfc  = (const float*)d_in[16];
    float* out = (float*)d_out;

    cudaFuncSetAttribute(gemm_kernel, cudaFuncAttributeMaxDynamicSharedMemorySize,
                         GEMM_SMEM);

    repack_kernel<<<(4 * 512 * HID + 255) / 256, 256>>>(Wf, Ws);
    embed_kernel<<<(NN * 32 + 255) / 256, 256>>>(x, Wn, bnd);
    csr_zero_kernel<<<(NN + 255) / 256, 256>>>();
    csr_count_kernel<<<(EE + 255) / 256, 256>>>(ei);
    csr_scan_kernel<<<1, 1024>>>();
    csr_scatter_kernel<<<(EE + 255) / 256, 256>>>(ei, dist);
    zero_kernel<<<512, 256>>>();   // layer-0 agg zero; update re-zeroes afterwards

    for (int l = 0; l < 4; l++) {
        dim3 gg((NN + 127) / 128, 512 / 128);
        gemm_kernel<<<gg, 512, GEMM_SMEM>>>(l, bf + l * HID, bs + l * HID);
        edge_kernel<<<EE / 128, 256>>>(Wf + (size_t)l * 272 * HID + 256 * HID,
                                       Ws + (size_t)l * 272 * HID + 256 * HID);
        bnstats_kernel<<<512, HID>>>();
        update_kernel<<<(NN * 32 + 255) / 256, 256>>>(bng + l * HID, bnb + l * HID,
                                                      lng + l * HID, lnb + l * HID);
    }
    final_kernel<<<(NN * 32 + 255) / 256, 256>>>(lgo, lbo, Wfc, bfc, out);
}

// round 15
// speedup vs baseline: 1.5671x; 1.0096x over previous
#include <cuda_runtime.h>
#include <cuda_bf16.h>
#include <cstdint>

#define NN   20000
#define EE   320000
#define HID  128
#define NCLS 21
#define EPSN 1e-5f
#define RBF_C (-1.7578125f)          /* -0.5/(8/15)^2 */
#define RBF_S (0.53333333333333333f) /* 8/15 */
#define ASTR 136                      /* padded bf16 row stride in smem tiles */
#define GEMM_SMEM (4 * 128 * ASTR * 2)

// ---------------- scratch (device globals; no allocation allowed) ----------
__device__ float g_h  [(size_t)NN * HID];   // node features (fp32)
__device__ __nv_bfloat16 g_hhi[(size_t)NN * HID];  // bf16 split of h
__device__ __nv_bfloat16 g_hlo[(size_t)NN * HID];
__device__ float g_P  [(size_t)NN * 512];   // per-node proj [f_dst|s_dst|f_src|s_src]
__device__ float g_agg[(size_t)NN * HID];   // aggregated messages
__device__ __nv_bfloat16 g_Whi[4 * 512 * HID];  // W transposed [l][n=512][k=128]
__device__ __nv_bfloat16 g_Wlo[4 * 512 * HID];
__device__ float g_cs [HID];                // BN column sums
__device__ float g_cq [HID];                // BN column sumsqs
// CSR scratch
__device__ int   g_cnt   [NN];
__device__ int   g_cursor[NN];
__device__ int   g_esrc  [EE];
__device__ int   g_edst  [EE];
__device__ float g_edist [EE];

// ---------------- helpers --------------------------------------------------
__device__ __forceinline__ float sigf(float x) {
    return __fdividef(1.0f, 1.0f + __expf(-x));
}
__device__ __forceinline__ float spf(float x) {  // softplus, stable
    return fmaxf(x, 0.0f) + __logf(1.0f + __expf(-fabsf(x)));
}
__device__ __forceinline__ void split_bf16(float x, __nv_bfloat16& hi, __nv_bfloat16& lo) {
    hi = __float2bfloat16_rn(x);
    lo = __float2bfloat16_rn(x - __bfloat162float(hi));
}
__device__ __forceinline__ void mma_bf16(float c[4], uint32_t a0, uint32_t a1,
                                         uint32_t a2, uint32_t a3,
                                         uint32_t b0, uint32_t b1) {
    asm volatile(
        "mma.sync.aligned.m16n8k16.row.col.f32.bf16.bf16.f32 "
        "{%0,%1,%2,%3}, {%4,%5,%6,%7}, {%8,%9}, {%0,%1,%2,%3};\n"
        : "+f"(c[0]), "+f"(c[1]), "+f"(c[2]), "+f"(c[3])
        : "r"(a0), "r"(a1), "r"(a2), "r"(a3), "r"(b0), "r"(b1));
}
__device__ __forceinline__ void ldsm_x4(uint32_t& r0, uint32_t& r1, uint32_t& r2,
                                        uint32_t& r3, uint32_t addr) {
    asm volatile("ldmatrix.sync.aligned.m8n8.x4.shared.b16 {%0,%1,%2,%3}, [%4];"
                 : "=r"(r0), "=r"(r1), "=r"(r2), "=r"(r3) : "r"(addr));
}
__device__ __forceinline__ void ldsm_x2(uint32_t& r0, uint32_t& r1, uint32_t addr) {
    asm volatile("ldmatrix.sync.aligned.m8n8.x2.shared.b16 {%0,%1}, [%2];"
                 : "=r"(r0), "=r"(r1) : "r"(addr));
}
__device__ __forceinline__ uint32_t smem_u32(const void* p) {
    return (uint32_t)__cvta_generic_to_shared(p);
}
// packed fp32x2 FMA (SASS FFMA2) — only reachable via PTX
__device__ __forceinline__ void ffma2(unsigned long long& c, unsigned long long a,
                                      unsigned long long b) {
    asm("fma.rn.f32x2 %0, %1, %2, %0;" : "+l"(c) : "l"(a), "l"(b));
}
__device__ __forceinline__ unsigned long long pack2(float v) {
    unsigned long long r;
    asm("mov.b64 %0, {%1, %1};" : "=l"(r) : "r"(__float_as_uint(v)));
    return r;
}
__device__ __forceinline__ float lo32f(unsigned long long v) {
    return __uint_as_float((uint32_t)v);
}
__device__ __forceinline__ float hi32f(unsigned long long v) {
    return __uint_as_float((uint32_t)(v >> 32));
}

// ---------------- repack Wf/Ws into bf16-split TRANSPOSED [4][512][128] -----
// n:  [0,128) f_dst | [128,256) s_dst | [256,384) f_src | [384,512) s_src
__global__ void repack_kernel(const float* __restrict__ Wf, const float* __restrict__ Ws) {
    int idx = blockIdx.x * blockDim.x + threadIdx.x;
    const int total = 4 * 512 * HID;
    if (idx >= total) return;
    int l   = idx / (512 * HID);
    int rem = idx - l * (512 * HID);
    int n   = rem >> 7;     // 0..511
    int k   = rem & 127;    // 0..127
    const float* Wfl = Wf + (size_t)l * 272 * HID;
    const float* Wsl = Ws + (size_t)l * 272 * HID;
    float v;
    if      (n < 128) v = Wfl[k * HID + n];
    else if (n < 256) v = Wsl[k * HID + (n - 128)];
    else if (n < 384) v = Wfl[(128 + k) * HID + (n - 256)];
    else              v = Wsl[(128 + k) * HID + (n - 384)];
    __nv_bfloat16 hi, lo;
    split_bf16(v, hi, lo);
    g_Whi[idx] = hi;
    g_Wlo[idx] = lo;
}

// ---------------- node embedding: h = x @ W_node + b ------------------------
__global__ void embed_kernel(const float* __restrict__ x, const float* __restrict__ Wn,
                             const float* __restrict__ bnode) {
    int gw   = (blockIdx.x * blockDim.x + threadIdx.x) >> 5;
    int lane = threadIdx.x & 31;
    if (gw >= NN) return;
    int j = lane * 4;
    float a[4] = {bnode[j], bnode[j + 1], bnode[j + 2], bnode[j + 3]};
    const float* xr = x + (size_t)gw * 6;
#pragma unroll
    for (int k = 0; k < 6; k++) {
        float xv = xr[k];
        const float* w = Wn + k * HID + j;
        a[0] += xv * w[0]; a[1] += xv * w[1]; a[2] += xv * w[2]; a[3] += xv * w[3];
    }
    *(float4*)(g_h + (size_t)gw * HID + j) = make_float4(a[0], a[1], a[2], a[3]);
#pragma unroll
    for (int t = 0; t < 4; t++) {
        __nv_bfloat16 hi, lo;
        split_bf16(a[t], hi, lo);
        g_hhi[(size_t)gw * HID + j + t] = hi;
        g_hlo[(size_t)gw * HID + j + t] = lo;
    }
}

// ---------------- CSR build --------------------------------------------------
__global__ void csr_zero_kernel() {
    int i = blockIdx.x * blockDim.x + threadIdx.x;
    if (i < NN) g_cnt[i] = 0;
}
__global__ void csr_count_kernel(const int* __restrict__ ei) {
    int e = blockIdx.x * blockDim.x + threadIdx.x;
    if (e < EE) atomicAdd(&g_cnt[ei[EE + e]], 1);
}
__global__ void csr_scan_kernel() {  // single block, 1024 threads
    __shared__ int sums[1024];
    int t = threadIdx.x;
    const int PER = (NN + 1023) / 1024;  // 20
    int base = t * PER;
    int s = 0;
    for (int i = 0; i < PER; i++) {
        int idx = base + i;
        if (idx < NN) s += g_cnt[idx];
    }
    sums[t] = s;
    __syncthreads();
    for (int o = 1; o < 1024; o <<= 1) {
        int v = (t >= o) ? sums[t - o] : 0;
        __syncthreads();
        sums[t] += v;
        __syncthreads();
    }
    int run = sums[t] - s;  // exclusive prefix
    for (int i = 0; i < PER; i++) {
        int idx = base + i;
        if (idx < NN) {
            g_cursor[idx] = run;
            run += g_cnt[idx];
        }
    }
}
__global__ void csr_scatter_kernel(const int* __restrict__ ei, const float* __restrict__ dist) {
    int e = blockIdx.x * blockDim.x + threadIdx.x;
    if (e >= EE) return;
    int src = ei[e];
    int dst = ei[EE + e];
    int pos = atomicAdd(&g_cursor[dst], 1);
    g_esrc[pos]  = src;
    g_edst[pos]  = dst;
    g_edist[pos] = dist[e];
}

// ---------------- tensor-core GEMM: P = h @ W[l]^T, full-K-resident ----------
__global__ __launch_bounds__(512)
void gemm_kernel(int layer, const float* __restrict__ bf_, const float* __restrict__ bs_) {
    extern __shared__ __align__(16) char smem_raw[];
    __nv_bfloat16* Ah = (__nv_bfloat16*)smem_raw;          // [128][ASTR]
    __nv_bfloat16* Al = Ah + 128 * ASTR;
    __nv_bfloat16* Bh = Al + 128 * ASTR;                   // [128 n][ASTR k]
    __nv_bfloat16* Bl = Bh + 128 * ASTR;

    const __nv_bfloat16* Wh = g_Whi + (size_t)layer * 512 * HID;
    const __nv_bfloat16* Wl = g_Wlo + (size_t)layer * 512 * HID;
    int bm = blockIdx.x * 128, bn = blockIdx.y * 128;
    int tid = threadIdx.x;

#pragma unroll
    for (int r = 0; r < 4; r++) {
        int idx = tid + r * 512;          // 0..2047
        int row = idx >> 4, c8 = (idx & 15) * 8;
        int gm = bm + row;
        uint4 vh = make_uint4(0u, 0u, 0u, 0u), vl = vh;
        if (gm < NN) {
            vh = *(const uint4*)&g_hhi[(size_t)gm * HID + c8];
            vl = *(const uint4*)&g_hlo[(size_t)gm * HID + c8];
        }
        *(uint4*)&Ah[row * ASTR + c8] = vh;
        *(uint4*)&Al[row * ASTR + c8] = vl;
    }
#pragma unroll
    for (int r = 0; r < 4; r++) {
        int idx = tid + r * 512;
        int row = idx >> 4, c8 = (idx & 15) * 8;
        *(uint4*)&Bh[row * ASTR + c8] = *(const uint4*)&Wh[(size_t)(bn + row) * HID + c8];
        *(uint4*)&Bl[row * ASTR + c8] = *(const uint4*)&Wl[(size_t)(bn + row) * HID + c8];
    }
    __syncthreads();

    int warp = tid >> 5, lane = tid & 31;
    int wm = (warp >> 2) * 32, wn = (warp & 3) * 32;

    float acc[2][4][4];
#pragma unroll
    for (int mi = 0; mi < 2; mi++)
#pragma unroll
        for (int nj = 0; nj < 4; nj++)
#pragma unroll
            for (int t = 0; t < 4; t++) acc[mi][nj][t] = 0.0f;

    uint32_t aBase = smem_u32(Ah), bBase = smem_u32(Bh);
    const uint32_t HILO_A = (uint32_t)(128 * ASTR * 2);
    int arow = wm + (lane & 15);
    int akof = (lane >> 4) * 8;
    int brow = wn + (lane & 7);
    int bkof = ((lane >> 3) & 1) * 8;

#pragma unroll
    for (int ks = 0; ks < 8; ks++) {
        int k0 = ks * 16;
        uint32_t ah[2][4], al[2][4], bh[4][2], bl[4][2];
#pragma unroll
        for (int mi = 0; mi < 2; mi++) {
            uint32_t ad = aBase + (uint32_t)(((arow + mi * 16) * ASTR + k0 + akof) * 2);
            ldsm_x4(ah[mi][0], ah[mi][1], ah[mi][2], ah[mi][3], ad);
            ldsm_x4(al[mi][0], al[mi][1], al[mi][2], al[mi][3], ad + HILO_A);
        }
#pragma unroll
        for (int nj = 0; nj < 4; nj++) {
            uint32_t bd = bBase + (uint32_t)(((brow + nj * 8) * ASTR + k0 + bkof) * 2);
            ldsm_x2(bh[nj][0], bh[nj][1], bd);
            ldsm_x2(bl[nj][0], bl[nj][1], bd + HILO_A);
        }
#pragma unroll
        for (int mi = 0; mi < 2; mi++)
#pragma unroll
            for (int nj = 0; nj < 4; nj++) {
                mma_bf16(acc[mi][nj], ah[mi][0], ah[mi][1], ah[mi][2], ah[mi][3],
                         bh[nj][0], bh[nj][1]);
                mma_bf16(acc[mi][nj], ah[mi][0], ah[mi][1], ah[mi][2], ah[mi][3],
                         bl[nj][0], bl[nj][1]);
                mma_bf16(acc[mi][nj], al[mi][0], al[mi][1], al[mi][2], al[mi][3],
                         bh[nj][0], bh[nj][1]);
            }
    }

    if (blockIdx.x == 0 && blockIdx.y == 0 && tid < HID) {
        g_cs[tid] = 0.0f;
        g_cq[tid] = 0.0f;
    }

    const float* bptr = (bn == 0) ? bf_ : ((bn == 128) ? bs_ : (const float*)0);
    int crow = lane >> 2, ccol = (lane & 3) * 2;
#pragma unroll
    for (int mi = 0; mi < 2; mi++) {
        int gm0 = bm + wm + mi * 16 + crow;
#pragma unroll
        for (int nj = 0; nj < 4; nj++) {
            int lcol = wn + nj * 8 + ccol;
            float b0 = bptr ? bptr[lcol] : 0.0f;
            float b1 = bptr ? bptr[lcol + 1] : 0.0f;
            int gn = bn + lcol;
            if (gm0 < NN) {
                float2 v = make_float2(acc[mi][nj][0] + b0, acc[mi][nj][1] + b1);
                *(float2*)&g_P[(size_t)gm0 * 512 + gn] = v;
            }
            if (gm0 + 8 < NN) {
                float2 v = make_float2(acc[mi][nj][2] + b0, acc[mi][nj][3] + b1);
                *(float2*)&g_P[(size_t)(gm0 + 8) * 512 + gn] = v;
            }
        }
    }
}

// ---------------- zero agg (once, before layer 0) ----------------------------
__global__ void zero_kernel() {
    int i = blockIdx.x * blockDim.x + threadIdx.x;
    int stride = gridDim.x * blockDim.x;
    for (int idx = i; idx < NN * HID; idx += stride) g_agg[idx] = 0.0f;
}

// ---------------- edge kernel: 128 CSR edges/block, FFMA2 mainloop ----------
__global__ __launch_bounds__(256, 2)
void edge_kernel(const float* __restrict__ WfE, const float* __restrict__ WsE) {
    __shared__ float W_s[16 * 256];                 // [k][0..127]=Wef, [128..255]=Wes
    __shared__ unsigned long long E2[128 * 17];     // packed {v,v} RBF values
    __shared__ float s_dist[128];
    __shared__ int   s_src[128];
    __shared__ int   s_dst[128];
    int tid = threadIdx.x;
    int eb = blockIdx.x * 128;
#pragma unroll
    for (int i = tid; i < 2048; i += 256) {
        int k = i >> 7, j = i & 127;
        W_s[(k << 8) + j]       = WfE[i];
        W_s[(k << 8) + 128 + j] = WsE[i];
    }
    if (tid < 128) {
        int e = eb + tid;
        s_src[tid]  = g_esrc[e];
        s_dst[tid]  = g_edst[e];
        s_dist[tid] = g_edist[e];
    }
    __syncthreads();
#pragma unroll
    for (int i = tid; i < 2048; i += 256) {
        int le = i >> 4, k = i & 15;
        float t = s_dist[le] - (float)k * RBF_S;
        E2[le * 17 + k] = pack2(__expf(RBF_C * t * t));
    }
    __syncthreads();

    int c = tid & 31, g = tid >> 5;
    int j4 = c * 4;

#pragma unroll
    for (int h = 0; h < 2; h++) {
        unsigned long long acc2[8][4];   // [edge][pair]: f01,f23,s01,s23
#pragma unroll
        for (int i = 0; i < 8; i++)
#pragma unroll
            for (int j = 0; j < 4; j++) acc2[i][j] = 0ull;

#pragma unroll
        for (int k = 0; k < 16; k++) {
            unsigned long long wf0 = *(const unsigned long long*)&W_s[(k << 8) + j4];
            unsigned long long wf1 = *(const unsigned long long*)&W_s[(k << 8) + j4 + 2];
            unsigned long long ws0 = *(const unsigned long long*)&W_s[(k << 8) + 128 + j4];
            unsigned long long ws1 = *(const unsigned long long*)&W_s[(k << 8) + 128 + j4 + 2];
#pragma unroll
            for (int i = 0; i < 8; i++) {
                unsigned long long a = E2[(h * 64 + g * 8 + i) * 17 + k];  // broadcast
                ffma2(acc2[i][0], a, wf0);
                ffma2(acc2[i][1], a, wf1);
                ffma2(acc2[i][2], a, ws0);
                ffma2(acc2[i][3], a, ws1);
            }
        }

        // epilogue: gather P (dst rows cached), activations, run-length atomics
        int cur = -1, prevdst = -1;
        float m0 = 0.f, m1 = 0.f, m2 = 0.f, m3 = 0.f;
        float4 fd = make_float4(0.f, 0.f, 0.f, 0.f), sd = fd;
#pragma unroll
        for (int i = 0; i < 8; i++) {
            int le = h * 64 + g * 8 + i;
            int src = s_src[le], dst = s_dst[le];
            if (dst != prevdst) {
                const float* pd = g_P + (size_t)dst * 512;
                fd = *(const float4*)(pd + j4);
                sd = *(const float4*)(pd + 128 + j4);
                prevdst = dst;
            }
            const float* ps = g_P + (size_t)src * 512;
            float4 fs = *(const float4*)(ps + 256 + j4);
            float4 ss = *(const float4*)(ps + 384 + j4);
            float f0 = lo32f(acc2[i][0]) + fd.x + fs.x;
            float f1 = hi32f(acc2[i][0]) + fd.y + fs.y;
            float f2 = lo32f(acc2[i][1]) + fd.z + fs.z;
            float f3 = hi32f(acc2[i][1]) + fd.w + fs.w;
            float s0 = lo32f(acc2[i][2]) + sd.x + ss.x;
            float s1 = hi32f(acc2[i][2]) + sd.y + ss.y;
            float s2 = lo32f(acc2[i][3]) + sd.z + ss.z;
            float s3 = hi32f(acc2[i][3]) + sd.w + ss.w;
            float q0 = sigf(f0) * spf(s0);
            float q1 = sigf(f1) * spf(s1);
            float q2 = sigf(f2) * spf(s2);
            float q3 = sigf(f3) * spf(s3);
            if (dst != cur) {
                if (cur >= 0) {
                    float* ap = g_agg + (size_t)cur * HID + j4;
                    atomicAdd(ap + 0, m0); atomicAdd(ap + 1, m1);
                    atomicAdd(ap + 2, m2); atomicAdd(ap + 3, m3);
                }
                cur = dst;
                m0 = q0; m1 = q1; m2 = q2; m3 = q3;
            } else {
                m0 += q0; m1 += q1; m2 += q2; m3 += q3;
            }
        }
        if (cur >= 0) {
            float* ap = g_agg + (size_t)cur * HID + j4;
            atomicAdd(ap + 0, m0); atomicAdd(ap + 1, m1);
            atomicAdd(ap + 2, m2); atomicAdd(ap + 3, m3);
        }
    }
}

// ---------------- BN column stats -------------------------------------------
__global__ void bnstats_kernel() {
    int jj = threadIdx.x;  // 128 threads
    float s = 0.0f, q = 0.0f;
    for (int r = blockIdx.x; r < NN; r += gridDim.x) {
        float v = g_agg[(size_t)r * HID + jj];
        s += v;
        q += v * v;
    }
    atomicAdd(&g_cs[jj], s);
    atomicAdd(&g_cq[jj], q);
}

// ---------------- fused BN + residual + LN + ReLU + residual + re-zero ------
__global__ void update_kernel(const float* __restrict__ bng, const float* __restrict__ bnb,
                              const float* __restrict__ lng, const float* __restrict__ lnb) {
    int gw   = (blockIdx.x * blockDim.x + threadIdx.x) >> 5;
    int lane = threadIdx.x & 31;
    if (gw >= NN) return;
    int j = lane * 4;
    float4 a  = *(const float4*)(g_agg + (size_t)gw * HID + j);
    float4 hv = *(const float4*)(g_h   + (size_t)gw * HID + j);
    float4 cs = *(const float4*)(g_cs + j);
    float4 cq = *(const float4*)(g_cq + j);
    float4 gg = *(const float4*)(bng + j);
    float4 bb = *(const float4*)(bnb + j);
    // re-zero agg for the next layer (replaces standalone zero_kernel)
    *(float4*)(g_agg + (size_t)gw * HID + j) = make_float4(0.f, 0.f, 0.f, 0.f);
    const float invN = 1.0f / (float)NN;
    float av[4]  = {a.x, a.y, a.z, a.w};
    float hh[4]  = {hv.x, hv.y, hv.z, hv.w};
    float csv[4] = {cs.x, cs.y, cs.z, cs.w};
    float cqv[4] = {cq.x, cq.y, cq.z, cq.w};
    float ggv[4] = {gg.x, gg.y, gg.z, gg.w};
    float bbv[4] = {bb.x, bb.y, bb.z, bb.w};
    float cvals[4];
    float sum = 0.0f, sq = 0.0f;
#pragma unroll
    for (int t = 0; t < 4; t++) {
        float mu  = csv[t] * invN;
        float var = cqv[t] * invN - mu * mu;
        float an  = (av[t] - mu) * rsqrtf(var + EPSN) * ggv[t] + bbv[t];
        cvals[t] = an + hh[t];
        sum += cvals[t];
        sq  += cvals[t] * cvals[t];
    }
#pragma unroll
    for (int o = 16; o; o >>= 1) {
        sum += __shfl_xor_sync(0xffffffffu, sum, o);
        sq  += __shfl_xor_sync(0xffffffffu, sq, o);
    }
    float m  = sum * (1.0f / HID);
    float v  = sq * (1.0f / HID) - m * m;
    float rs = rsqrtf(v + EPSN);
    float4 lg = *(const float4*)(lng + j);
    float4 lb = *(const float4*)(lnb + j);
    float lgv[4] = {lg.x, lg.y, lg.z, lg.w};
    float lbv[4] = {lb.x, lb.y, lb.z, lb.w};
    float o4[4];
#pragma unroll
    for (int t = 0; t < 4; t++)
        o4[t] = fmaxf((cvals[t] - m) * rs * lgv[t] + lbv[t], 0.0f) + hh[t];
    *(float4*)(g_h + (size_t)gw * HID + j) = make_float4(o4[0], o4[1], o4[2], o4[3]);
#pragma unroll
    for (int t = 0; t < 4; t++) {
        __nv_bfloat16 hi, lo;
        split_bf16(o4[t], hi, lo);
        g_hhi[(size_t)gw * HID + j + t] = hi;
        g_hlo[(size_t)gw * HID + j + t] = lo;
    }
}

// ---------------- final LN + FC ---------------------------------------------
__global__ void final_kernel(const float* __restrict__ lng, const float* __restrict__ lnb,
                             const float* __restrict__ Wfc, const float* __restrict__ bfc,
                             float* __restrict__ out) {
    int gw   = (blockIdx.x * blockDim.x + threadIdx.x) >> 5;
    int lane = threadIdx.x & 31;
    if (gw >= NN) return;
    int j = lane * 4;
    float4 hv = *(const float4*)(g_h + (size_t)gw * HID + j);
    float hh[4] = {hv.x, hv.y, hv.z, hv.w};
    float sum = hh[0] + hh[1] + hh[2] + hh[3];
    float sq  = hh[0] * hh[0] + hh[1] * hh[1] + hh[2] * hh[2] + hh[3] * hh[3];
#pragma unroll
    for (int o = 16; o; o >>= 1) {
        sum += __shfl_xor_sync(0xffffffffu, sum, o);
        sq  += __shfl_xor_sync(0xffffffffu, sq, o);
    }
    float m  = sum * (1.0f / HID);
    float v  = sq * (1.0f / HID) - m * m;
    float rs = rsqrtf(v + EPSN);
    float4 lg = *(const float4*)(lng + j);
    float4 lb = *(const float4*)(lnb + j);
    float hn[4];
    hn[0] = (hh[0] - m) * rs * lg.x + lb.x;
    hn[1] = (hh[1] - m) * rs * lg.y + lb.y;
    hn[2] = (hh[2] - m) * rs * lg.z + lb.z;
    hn[3] = (hh[3] - m) * rs * lg.w + lb.w;
#pragma unroll
    for (int c = 0; c < NCLS; c++) {
        float p = hn[0] * Wfc[(j + 0) * NCLS + c]
                + hn[1] * Wfc[(j + 1) * NCLS + c]
                + hn[2] * Wfc[(j + 2) * NCLS + c]
                + hn[3] * Wfc[(j + 3) * NCLS + c];
#pragma unroll
        for (int o = 16; o; o >>= 1) p += __shfl_xor_sync(0xffffffffu, p, o);
        if (lane == 0) out[(size_t)gw * NCLS + c] = p + bfc[c];
    }
}

// ---------------- launch (exact R12 ordering) --------------------------------
extern "C" void kernel_launch(void* const* d_in, const int* in_sizes, int n_in,
                              void* d_out, int out_size) {
    const float* x    = (const float*)d_in[0];
    const int*   ei   = (const int*)d_in[1];
    const float* dist = (const float*)d_in[2];
    const float* Wn   = (const float*)d_in[3];
    const float* bnd  = (const float*)d_in[4];
    const float* Wf   = (const float*)d_in[5];
    const float* bf   = (const float*)d_in[6];
    const float* Ws   = (const float*)d_in[7];
    const float* bs   = (const float*)d_in[8];
    const float* bng  = (const float*)d_in[9];
    const float* bnb  = (const float*)d_in[10];
    const float* lng  = (const float*)d_in[11];
    const float* lnb  = (const float*)d_in[12];
    const float* lgo  = (const float*)d_in[13];
    const float* lbo  = (const float*)d_in[14];
    const float* Wfc  = (const float*)d_in[15];
    const float* bfc  = (const float*)d_in[16];
    float* out = (float*)d_out;

    cudaFuncSetAttribute(gemm_kernel, cudaFuncAttributeMaxDynamicSharedMemorySize,
                         GEMM_SMEM);

    repack_kernel<<<(4 * 512 * HID + 255) / 256, 256>>>(Wf, Ws);
    embed_kernel<<<(NN * 32 + 255) / 256, 256>>>(x, Wn, bnd);
    csr_zero_kernel<<<(NN + 255) / 256, 256>>>();
    csr_count_kernel<<<(EE + 255) / 256, 256>>>(ei);
    csr_scan_kernel<<<1, 1024>>>();
    csr_scatter_kernel<<<(EE + 255) / 256, 256>>>(ei, dist);
    zero_kernel<<<512, 256>>>();   // layer-0 agg zero; update re-zeroes afterwards

    for (int l = 0; l < 4; l++) {
        dim3 gg((NN + 127) / 128, 512 / 128);
        gemm_kernel<<<gg, 512, GEMM_SMEM>>>(l, bf + l * HID, bs + l * HID);
        edge_kernel<<<EE / 128, 256>>>(Wf + (size_t)l * 272 * HID + 256 * HID,
                                       Ws + (size_t)l * 272 * HID + 256 * HID);
        bnstats_kernel<<<512, HID>>>();
        update_kernel<<<(NN * 32 + 255) / 256, 256>>>(bng + l * HID, bnb + l * HID,
                                                      lng + l * HID, lnb + l * HID);
    }
    final_kernel<<<(NN * 32 + 255) / 256, 256>>>(lgo, lbo, Wfc, bfc, out);
}